// round 14
// baseline (speedup 1.0000x reference)
#include <cuda_runtime.h>
#include <cuda_fp16.h>
#include <math.h>
#include <stdint.h>

// ---------------------------------------------------------------------------
// MiniTransformer forward: B=16, T=1024, D=512, H=8, HS=64, L=6, FF=2048, V=96
// Output: logits [16384, 96] (fp32) followed by scalar loss.
// GEMMs: fp16 m16n8k16, 64x64 warp tiles, 128-thread CTAs, cp.async.
// Attention: fp16 mma flash attention, P kept in registers.
// ---------------------------------------------------------------------------

#define B_   16
#define T_   1024
#define D_   512
#define H_   8
#define HS_  64
#define L_   6
#define FF_  2048
#define V_   96
#define BT_  (B_ * T_)

// ------------------------- device scratch (no mallocs) ---------------------
__device__ float g_x   [BT_ * D_];          // residual stream (fp32)
__device__ half  g_h   [BT_ * D_];          // LN output (fp16)
__device__ half  g_qkv [BT_ * 3 * D_];      // q|k|v per token (fp16)
__device__ half  g_o   [BT_ * D_];          // attention output (fp16)
__device__ half  g_ff  [BT_ * FF_];         // FFN hidden (fp16)
// weights transposed to [n][k], fp16
__device__ half  g_wqkv [L_ * 3 * D_ * D_];
__device__ half  g_wproj[L_ * D_ * D_];
__device__ half  g_w1   [L_ * FF_ * D_];
__device__ half  g_w2   [L_ * D_ * FF_];
__device__ half  g_wout [V_ * D_];
__device__ double g_loss;

// ------------------------- helpers -----------------------------------------
__device__ __forceinline__ void cp16(uint32_t dst, const void* src, bool pred) {
    int sz = pred ? 16 : 0;
    asm volatile("cp.async.ca.shared.global [%0], [%1], 16, %2;\n"
                 :: "r"(dst), "l"(src), "r"(sz));
}
__device__ __forceinline__ void cp_commit() { asm volatile("cp.async.commit_group;\n"); }
__device__ __forceinline__ void cp_wait0()  { asm volatile("cp.async.wait_group 0;\n"); }

__device__ __forceinline__ void mma_f16(float* d, const uint32_t* a, const uint32_t* b) {
    asm volatile(
        "mma.sync.aligned.m16n8k16.row.col.f32.f16.f16.f32 "
        "{%0,%1,%2,%3}, {%4,%5,%6,%7}, {%8,%9}, {%0,%1,%2,%3};"
        : "+f"(d[0]), "+f"(d[1]), "+f"(d[2]), "+f"(d[3])
        : "r"(a[0]), "r"(a[1]), "r"(a[2]), "r"(a[3]), "r"(b[0]), "r"(b[1]));
}
__device__ __forceinline__ void ldsm_x4(uint32_t* r, uint32_t addr) {
    asm volatile("ldmatrix.sync.aligned.m8n8.x4.shared.b16 {%0,%1,%2,%3}, [%4];"
                 : "=r"(r[0]), "=r"(r[1]), "=r"(r[2]), "=r"(r[3]) : "r"(addr));
}
__device__ __forceinline__ void ldsm_x4_t(uint32_t* r, uint32_t addr) {
    asm volatile("ldmatrix.sync.aligned.m8n8.x4.trans.shared.b16 {%0,%1,%2,%3}, [%4];"
                 : "=r"(r[0]), "=r"(r[1]), "=r"(r[2]), "=r"(r[3]) : "r"(addr));
}

// ------------------------- small kernels -----------------------------------
__global__ void zero_loss_kernel(double* a) { *a = 0.0; }

// W [Lc][K][N] fp32 -> out [Lc][N][K] fp16, coalesced via 32x32 smem tiles.
__global__ void pack_wt_kernel(const float* __restrict__ W,
                               half* __restrict__ out, int K, int N) {
    __shared__ float tile[32][33];
    int l  = blockIdx.z;
    int n0 = blockIdx.x * 32, k0 = blockIdx.y * 32;
    int tx = threadIdx.x, ty = threadIdx.y;
    const float* Wl = W + (size_t)l * K * N;
    #pragma unroll
    for (int i = 0; i < 4; i++)
        tile[ty + i * 8][tx] = Wl[(size_t)(k0 + ty + i * 8) * N + n0 + tx];
    __syncthreads();
    half* ol = out + (size_t)l * N * K;
    #pragma unroll
    for (int i = 0; i < 4; i++)
        ol[(size_t)(n0 + ty + i * 8) * K + k0 + tx] = __float2half(tile[tx][ty + i * 8]);
}

// Wq/Wk/Wv [L][H][D][HS] -> packed transposed [L][3D(n)][D(k)] fp16.
__global__ void pack_qkv_kernel(const float* __restrict__ Wq,
                                const float* __restrict__ Wk,
                                const float* __restrict__ Wv,
                                half* __restrict__ out) {
    __shared__ float tile[32][33];
    int bz  = blockIdx.z;               // l*24 + sel*8 + h
    int h   = bz & 7;
    int sel = (bz >> 3) % 3;
    int l   = bz / 24;
    const float* W = (sel == 0) ? Wq : (sel == 1) ? Wk : Wv;
    const float* Wb = W + (((size_t)l * H_ + h) * D_) * HS_;
    int k0 = blockIdx.x * 32, hs0 = blockIdx.y * 32;
    int tx = threadIdx.x, ty = threadIdx.y;
    #pragma unroll
    for (int i = 0; i < 4; i++)
        tile[ty + i * 8][tx] = Wb[(size_t)(k0 + ty + i * 8) * HS_ + hs0 + tx];
    __syncthreads();
    #pragma unroll
    for (int i = 0; i < 4; i++) {
        int n = sel * 512 + h * 64 + hs0 + ty + i * 8;
        out[((size_t)l * 1536 + n) * D_ + k0 + tx] = __float2half(tile[tx][ty + i * 8]);
    }
}

__global__ void embed_kernel(const int* __restrict__ idx,
                             const float* __restrict__ tok,
                             const float* __restrict__ pos,
                             float* __restrict__ x) {
    int i = blockIdx.x * blockDim.x + threadIdx.x;
    if (i >= BT_ * D_) return;
    int d  = i & (D_ - 1);
    int bt = i >> 9;
    int t  = bt & (T_ - 1);
    x[i] = tok[(size_t)idx[bt] * D_ + d] + pos[t * D_ + d];
}

// warp-per-row LN: 8 rows per 256-thread block, 16 elems/lane, shfl-only.
__global__ __launch_bounds__(256) void ln_kernel(const float* __restrict__ x,
                                                 const float* __restrict__ s,
                                                 const float* __restrict__ b,
                                                 half* __restrict__ out) {
    int warp = threadIdx.x >> 5, lane = threadIdx.x & 31;
    size_t row = (size_t)blockIdx.x * 8 + warp;
    const float4* xr = (const float4*)(x + row * D_);

    float4 v[4];
    #pragma unroll
    for (int i = 0; i < 4; i++) v[i] = xr[lane * 4 + i];

    float sum = 0.f;
    #pragma unroll
    for (int i = 0; i < 4; i++) sum += v[i].x + v[i].y + v[i].z + v[i].w;
    #pragma unroll
    for (int o = 16; o; o >>= 1) sum += __shfl_xor_sync(0xffffffffu, sum, o);
    float mean = sum * (1.0f / D_);

    float vs = 0.f;
    #pragma unroll
    for (int i = 0; i < 4; i++) {
        float dx = v[i].x - mean, dy = v[i].y - mean;
        float dz = v[i].z - mean, dw = v[i].w - mean;
        vs += dx * dx + dy * dy + dz * dz + dw * dw;
    }
    #pragma unroll
    for (int o = 16; o; o >>= 1) vs += __shfl_xor_sync(0xffffffffu, vs, o);
    float inv = rsqrtf(vs * (1.0f / D_) + 1e-5f);

    const float4* sp = (const float4*)s;
    const float4* bp = (const float4*)b;
    half2 h2[8];
    #pragma unroll
    for (int i = 0; i < 4; i++) {
        float4 sv = sp[lane * 4 + i];
        float4 bv = bp[lane * 4 + i];
        float y0 = (v[i].x - mean) * inv * sv.x + bv.x;
        float y1 = (v[i].y - mean) * inv * sv.y + bv.y;
        float y2 = (v[i].z - mean) * inv * sv.z + bv.z;
        float y3 = (v[i].w - mean) * inv * sv.w + bv.w;
        h2[2 * i + 0] = __floats2half2_rn(y0, y1);
        h2[2 * i + 1] = __floats2half2_rn(y2, y3);
    }
    uint4* orow = (uint4*)(out + row * D_ + lane * 16);
    orow[0] = *(uint4*)&h2[0];
    orow[1] = *(uint4*)&h2[4];
}

// ------------------------- FP16 tensor-core GEMM ---------------------------
// C[M,N] = A[M,K] * B^T[N,K]   (A [m][k] fp16, B [n][k] fp16)
// mode: 0 = fp16 store (QKV); 1 = +bias fp32 (logits);
//       2 = +bias relu fp16 (FF1); 3 = +bias +residual fp32 (proj, FF2)
// 128x128 CTA tile, 128 threads = 4 warps, warp tile 64(m) x 64(n), BK=32.
// smem rows 40 halves (80B); 2-stage double buffer.
#define BK2 32
#define GROWB 80                 // row stride bytes
#define GBUFB (128 * 80)         // one buffer (one array) bytes = 10240
#define GEMM_SMEM (4 * GBUFB)    // 2 stages x (A + B) = 40960

__global__ __launch_bounds__(128, 2) void tgemm_kernel(
    const half* __restrict__ A, const half* __restrict__ Bm,
    const float* __restrict__ bias, const float* __restrict__ res,
    float* __restrict__ Cf, half* __restrict__ Ch,
    int M, int N, int K, int mode)
{
    extern __shared__ __align__(16) half smg[];
    uint32_t smBase = (uint32_t)__cvta_generic_to_shared(smg);
    const uint32_t BOFF = 2 * GBUFB;    // B buffers after 2 A buffers

    int tid  = threadIdx.x;
    int wid  = tid >> 5;
    int lane = tid & 31;
    int grp  = lane >> 2;
    int tig  = lane & 3;
    int warp_m = (wid & 1) * 64;
    int warp_n = (wid >> 1) * 64;

    // loaders: row = tid, 4 chunks of 16B per array per stage
    const half* Ap = A + (size_t)(blockIdx.y * 128 + tid) * K;
    int gn = blockIdx.x * 128 + tid;
    bool bp = gn < N;
    const half* Bp = Bm + (size_t)(bp ? gn : 0) * K;
    uint32_t aDst = smBase + tid * GROWB;
    uint32_t bDst = smBase + BOFF + tid * GROWB;

    // ldmatrix fragment bases (buffer 0)
    uint32_t aLd = smBase + (warp_m + (lane & 7) + ((lane >> 3) & 1) * 8) * GROWB
                 + (lane >> 4) * 16;
    uint32_t bLd = smBase + BOFF + (warp_n + (lane & 7) + (lane >> 4) * 8) * GROWB
                 + ((lane >> 3) & 1) * 16;

    float acc[4][8][4];
    #pragma unroll
    for (int i = 0; i < 4; i++)
        #pragma unroll
        for (int j = 0; j < 8; j++)
            #pragma unroll
            for (int r = 0; r < 4; r++) acc[i][j][r] = 0.f;

    int nstage = K / BK2;

    // prologue: stage 0 -> buffer 0
    #pragma unroll
    for (int c = 0; c < 4; c++) {
        cp16(aDst + c * 16, Ap + c * 8, true);
        cp16(bDst + c * 16, Bp + c * 8, bp);
    }
    cp_commit();
    cp_wait0();
    __syncthreads();

    int cur = 0;
    for (int s = 0; s < nstage; s++) {
        if (s + 1 < nstage) {
            int k0 = (s + 1) * BK2;
            uint32_t io = (cur ^ 1) * GBUFB;
            #pragma unroll
            for (int c = 0; c < 4; c++) {
                cp16(aDst + io + c * 16, Ap + k0 + c * 8, true);
                cp16(bDst + io + c * 16, Bp + k0 + c * 8, bp);
            }
            cp_commit();
        }

        uint32_t bo = cur * GBUFB;
        #pragma unroll
        for (int ks = 0; ks < 2; ks++) {
            uint32_t af[4][4];
            #pragma unroll
            for (int i = 0; i < 4; i++)
                ldsm_x4(af[i], aLd + bo + i * (16 * GROWB) + ks * 32);
            uint32_t bq[4][4];
            #pragma unroll
            for (int jb = 0; jb < 4; jb++)
                ldsm_x4(bq[jb], bLd + bo + jb * (16 * GROWB) + ks * 32);
            #pragma unroll
            for (int i = 0; i < 4; i++)
                #pragma unroll
                for (int j = 0; j < 8; j++)
                    mma_f16(acc[i][j], af[i], &bq[j >> 1][2 * (j & 1)]);
        }

        if (s + 1 < nstage) {
            cp_wait0();
            __syncthreads();
            cur ^= 1;
        }
    }

    #pragma unroll
    for (int i = 0; i < 4; i++) {
        int row0 = blockIdx.y * 128 + warp_m + i * 16 + grp;
        #pragma unroll
        for (int j = 0; j < 8; j++) {
            int col = blockIdx.x * 128 + warp_n + j * 8 + 2 * tig;
            if (col < N) {
                #pragma unroll
                for (int hf = 0; hf < 2; hf++) {
                    int r = row0 + hf * 8;
                    size_t rb = (size_t)r * N;
                    float v0 = acc[i][j][hf * 2 + 0];
                    float v1 = acc[i][j][hf * 2 + 1];
                    if (mode >= 1) { v0 += bias[col]; v1 += bias[col + 1]; }
                    if (mode == 2) { v0 = fmaxf(v0, 0.f); v1 = fmaxf(v1, 0.f); }
                    if (mode == 0 || mode == 2) {
                        *(half2*)(Ch + rb + col) = __floats2half2_rn(v0, v1);
                    } else {
                        if (mode == 3) { v0 += res[rb + col]; v1 += res[rb + col + 1]; }
                        *(float2*)(Cf + rb + col) = make_float2(v0, v1);
                    }
                }
            }
        }
    }
}

// ------------------------- fp16 flash attention (P in registers) -----------
// 128 queries/block, 8 warps x 16 query-rows, 64-key tiles double-buffered.
#define KROWB 144
#define KVBUF (64 * KROWB)            // 9216
#define ATTN_SMEM (4 * KVBUF)         // 36864

__global__ __launch_bounds__(256, 2) void attn_kernel(const half* __restrict__ QKV,
                                                      half* __restrict__ O) {
    extern __shared__ __align__(16) half sma[];
    uint32_t smBase = (uint32_t)__cvta_generic_to_shared(sma);

    int b = blockIdx.y >> 3, h = blockIdx.y & 7;
    int qb = blockIdx.x * 128;
    int tid = threadIdx.x, wid = tid >> 5, lane = tid & 31;
    int grp = lane >> 2, tig = lane & 3;
    const float scale2 = 0.04419417382415922f * 1.4426950408889634f;

    int lr0 = wid * 16 + grp;
    int lr1 = lr0 + 8;
    int gr0 = qb + lr0, gr1 = qb + lr1;

    const half* q0p = QKV + ((size_t)(b * T_) + gr0) * 1536 + h * 64;
    const half* q1p = QKV + ((size_t)(b * T_) + gr1) * 1536 + h * 64;
    uint32_t qa[4][4];
    #pragma unroll
    for (int k = 0; k < 4; k++) {
        int dd = 16 * k + 2 * tig;
        #pragma unroll
        for (int r = 0; r < 4; r++) {
            const half* qp = (r & 1) ? q1p : q0p;
            int d2 = dd + (r >> 1) * 8;
            float2 f = __half22float2(*(const half2*)(qp + d2));
            half2 hv = __floats2half2_rn(f.x * scale2, f.y * scale2);
            qa[k][r] = *(uint32_t*)&hv;
        }
    }

    uint32_t kLd = smBase + ((lane & 7) + (lane >> 4) * 8) * KROWB
                 + ((lane >> 3) & 1) * 16;
    uint32_t vLd = smBase + 2 * KVBUF + ((lane & 7) + ((lane >> 3) & 1) * 8) * KROWB
                 + (lane >> 4) * 16;

    int key4 = tid >> 2, c4 = tid & 3;
    int dh = 8 * c4;
    uint32_t kDst = smBase + key4 * KROWB + dh * 2;
    uint32_t vDst = kDst + 2 * KVBUF;
    const half* kvb = QKV + (size_t)(b * T_) * 1536 + h * 64 + D_;
    const half* kRow = kvb + (size_t)key4 * 1536 + dh;

    float o[8][4];
    #pragma unroll
    for (int j = 0; j < 8; j++) { o[j][0] = o[j][1] = o[j][2] = o[j][3] = 0.f; }
    float m0 = -1e30f, m1 = -1e30f, l0 = 0.f, l1 = 0.f;

    int ntiles = (qb >> 6) + 2;

    {
        cp16(kDst,      kRow,        true);
        cp16(kDst + 64, kRow + 32,   true);
        cp16(vDst,      kRow + 512,  true);
        cp16(vDst + 64, kRow + 544,  true);
        cp_commit();
    }

    for (int t = 0; t < ntiles; t++) {
        cp_wait0();
        __syncthreads();

        if (t + 1 < ntiles) {
            uint32_t io = ((t + 1) & 1) * KVBUF;
            const half* kr = kRow + (size_t)(t + 1) * 64 * 1536;
            cp16(kDst + io,      kr,       true);
            cp16(kDst + io + 64, kr + 32,  true);
            cp16(vDst + io,      kr + 512, true);
            cp16(vDst + io + 64, kr + 544, true);
            cp_commit();
        }

        uint32_t bo = (t & 1) * KVBUF;
        int k0 = t * 64;

        float sc[8][4];
        #pragma unroll
        for (int j = 0; j < 8; j++) { sc[j][0] = sc[j][1] = sc[j][2] = sc[j][3] = 0.f; }
        #pragma unroll
        for (int kd = 0; kd < 4; kd++) {
            uint32_t kq[4][4];
            #pragma unroll
            for (int jp = 0; jp < 4; jp++)
                ldsm_x4(kq[jp], kLd + bo + jp * (16 * KROWB) + kd * 32);
            #pragma unroll
            for (int j = 0; j < 8; j++)
                mma_f16(sc[j], qa[kd], &kq[j >> 1][2 * (j & 1)]);
        }

        if (k0 + 63 > qb + wid * 16) {
            #pragma unroll
            for (int j = 0; j < 8; j++) {
                int key = k0 + 8 * j + 2 * tig;
                if (key     > gr0) sc[j][0] = -1e30f;
                if (key + 1 > gr0) sc[j][1] = -1e30f;
                if (key     > gr1) sc[j][2] = -1e30f;
                if (key + 1 > gr1) sc[j][3] = -1e30f;
            }
        }

        float mx0 = -1e30f, mx1 = -1e30f;
        #pragma unroll
        for (int j = 0; j < 8; j++) {
            mx0 = fmaxf(mx0, fmaxf(sc[j][0], sc[j][1]));
            mx1 = fmaxf(mx1, fmaxf(sc[j][2], sc[j][3]));
        }
        mx0 = fmaxf(mx0, __shfl_xor_sync(0xffffffffu, mx0, 1));
        mx0 = fmaxf(mx0, __shfl_xor_sync(0xffffffffu, mx0, 2));
        mx1 = fmaxf(mx1, __shfl_xor_sync(0xffffffffu, mx1, 1));
        mx1 = fmaxf(mx1, __shfl_xor_sync(0xffffffffu, mx1, 2));
        float mn0 = fmaxf(m0, mx0), mn1 = fmaxf(m1, mx1);
        float c0 = exp2f(m0 - mn0), c1 = exp2f(m1 - mn1);
        m0 = mn0; m1 = mn1;

        uint32_t pf[4][4];
        float s0 = 0.f, s1 = 0.f;
        #pragma unroll
        for (int k = 0; k < 4; k++) {
            float p00 = exp2f(sc[2 * k][0] - m0);
            float p01 = exp2f(sc[2 * k][1] - m0);
            float p02 = exp2f(sc[2 * k][2] - m1);
            float p03 = exp2f(sc[2 * k][3] - m1);
            float p10 = exp2f(sc[2 * k + 1][0] - m0);
            float p11 = exp2f(sc[2 * k + 1][1] - m0);
            float p12 = exp2f(sc[2 * k + 1][2] - m1);
            float p13 = exp2f(sc[2 * k + 1][3] - m1);
            s0 += p00 + p01 + p10 + p11;
            s1 += p02 + p03 + p12 + p13;
            half2 h0 = __floats2half2_rn(p00, p01);
            half2 h1 = __floats2half2_rn(p02, p03);
            half2 h2 = __floats2half2_rn(p10, p11);
            half2 h3 = __floats2half2_rn(p12, p13);
            pf[k][0] = *(uint32_t*)&h0;
            pf[k][1] = *(uint32_t*)&h1;
            pf[k][2] = *(uint32_t*)&h2;
            pf[k][3] = *(uint32_t*)&h3;
        }
        s0 += __shfl_xor_sync(0xffffffffu, s0, 1);
        s0 += __shfl_xor_sync(0xffffffffu, s0, 2);
        s1 += __shfl_xor_sync(0xffffffffu, s1, 1);
        s1 += __shfl_xor_sync(0xffffffffu, s1, 2);
        l0 = l0 * c0 + s0;
        l1 = l1 * c1 + s1;
        #pragma unroll
        for (int j = 0; j < 8; j++) {
            o[j][0] *= c0; o[j][1] *= c0; o[j][2] *= c1; o[j][3] *= c1;
        }

        #pragma unroll
        for (int kd = 0; kd < 4; kd++) {
            uint32_t vq[4][4];
            #pragma unroll
            for (int jp = 0; jp < 4; jp++)
                ldsm_x4_t(vq[jp], vLd + bo + kd * (16 * KROWB) + jp * 32);
            #pragma unroll
            for (int j = 0; j < 8; j++)
                mma_f16(o[j], pf[kd], &vq[j >> 1][2 * (j & 1)]);
        }
    }

    float i0 = 1.f / l0, i1 = 1.f / l1;
    size_t ob0 = ((size_t)(b * T_) + gr0) * D_ + h * 64;
    size_t ob1 = ((size_t)(b * T_) + gr1) * D_ + h * 64;
    #pragma unroll
    for (int j = 0; j < 8; j++) {
        int c = 8 * j + 2 * tig;
        *(half2*)(O + ob0 + c) = __floats2half2_rn(o[j][0] * i0, o[j][1] * i0);
        *(half2*)(O + ob1 + c) = __floats2half2_rn(o[j][2] * i1, o[j][3] * i1);
    }
}

// ------------------------- loss --------------------------------------------
__global__ __launch_bounds__(256) void loss_kernel(const float* __restrict__ logits,
                                                   const int* __restrict__ targets,
                                                   double* __restrict__ acc) {
    int warp = (blockIdx.x * blockDim.x + threadIdx.x) >> 5;
    int lane = threadIdx.x & 31;
    const float* lr = logits + (size_t)warp * V_;
    float v0 = lr[lane], v1 = lr[lane + 32], v2 = lr[lane + 64];
    float m = fmaxf(v0, fmaxf(v1, v2));
    #pragma unroll
    for (int o = 16; o; o >>= 1) m = fmaxf(m, __shfl_xor_sync(0xffffffffu, m, o));
    float se = expf(v0 - m) + expf(v1 - m) + expf(v2 - m);
    #pragma unroll
    for (int o = 16; o; o >>= 1) se += __shfl_xor_sync(0xffffffffu, se, o);

    __shared__ float part[8];
    if (lane == 0) part[threadIdx.x >> 5] = lr[targets[warp]] - m - logf(se);
    __syncthreads();
    if (threadIdx.x == 0) {
        float s = 0.f;
        #pragma unroll
        for (int i = 0; i < 8; i++) s += part[i];
        atomicAdd(acc, (double)s);
    }
}

__global__ void finalize_loss_kernel(float* out, const double* acc) {
    out[(size_t)BT_ * V_] = (float)(-(*acc) / (double)BT_);
}

// ------------------------- launcher ----------------------------------------
extern "C" void kernel_launch(void* const* d_in, const int* in_sizes, int n_in,
                              void* d_out, int out_size) {
    const int*   idx     = (const int*)  d_in[0];
    const int*   targets = (const int*)  d_in[1];
    const float* tok     = (const float*)d_in[2];
    const float* pos     = (const float*)d_in[3];
    const float* Wq      = (const float*)d_in[4];
    const float* Wk      = (const float*)d_in[5];
    const float* Wv      = (const float*)d_in[6];
    const float* Wproj   = (const float*)d_in[7];
    const float* bproj   = (const float*)d_in[8];
    const float* W1      = (const float*)d_in[9];
    const float* b1      = (const float*)d_in[10];
    const float* W2      = (const float*)d_in[11];
    const float* b2      = (const float*)d_in[12];
    const float* ln1_s   = (const float*)d_in[13];
    const float* ln1_b   = (const float*)d_in[14];
    const float* ln2_s   = (const float*)d_in[15];
    const float* ln2_b   = (const float*)d_in[16];
    const float* lnf_s   = (const float*)d_in[17];
    const float* lnf_b   = (const float*)d_in[18];
    const float* Wout    = (const float*)d_in[19];
    const float* bout    = (const float*)d_in[20];
    float* out = (float*)d_out;

    float* x;
    half *h, *qkv, *o, *ff, *wqkv, *wproj, *w1, *w2, *wout;
    double* lossAcc;
    cudaGetSymbolAddress((void**)&x,    g_x);
    cudaGetSymbolAddress((void**)&qkv,  g_qkv);
    cudaGetSymbolAddress((void**)&h,    g_h);
    cudaGetSymbolAddress((void**)&o,    g_o);
    cudaGetSymbolAddress((void**)&ff,   g_ff);
    cudaGetSymbolAddress((void**)&wqkv, g_wqkv);
    cudaGetSymbolAddress((void**)&wproj, g_wproj);
    cudaGetSymbolAddress((void**)&w1,   g_w1);
    cudaGetSymbolAddress((void**)&w2,   g_w2);
    cudaGetSymbolAddress((void**)&wout, g_wout);
    cudaGetSymbolAddress((void**)&lossAcc, g_loss);

    cudaFuncSetAttribute(tgemm_kernel,
                         cudaFuncAttributeMaxDynamicSharedMemorySize, GEMM_SMEM);
    cudaFuncSetAttribute(attn_kernel,
                         cudaFuncAttributeMaxDynamicSharedMemorySize, ATTN_SMEM);

    // weight packing (coalesced transposes, fp16)
    {
        dim3 blk(32, 8);
        pack_qkv_kernel<<<dim3(D_ / 32, HS_ / 32, L_ * 3 * H_), blk>>>(Wq, Wk, Wv, wqkv);
        pack_wt_kernel<<<dim3(D_ / 32, D_ / 32, L_), blk>>>(Wproj, wproj, D_, D_);
        pack_wt_kernel<<<dim3(FF_ / 32, D_ / 32, L_), blk>>>(W1, w1, D_, FF_);
        pack_wt_kernel<<<dim3(D_ / 32, FF_ / 32, L_), blk>>>(W2, w2, FF_, D_);
        pack_wt_kernel<<<dim3(V_ / 32, D_ / 32, 1), blk>>>(Wout, wout, D_, V_);
    }
    {
        int total = BT_ * D_;
        embed_kernel<<<(total + 255) / 256, 256>>>(idx, tok, pos, x);
    }

    const int MT = BT_ / 128;  // 128 M-tiles
    const int LNG = BT_ / 8;   // LN grid (8 rows/block)
    for (int l = 0; l < L_; l++) {
        ln_kernel<<<LNG, 256>>>(x, ln1_s + l * D_, ln1_b + l * D_, h);
        tgemm_kernel<<<dim3(12, MT), 128, GEMM_SMEM>>>(
            h, wqkv + (size_t)l * 3 * D_ * D_,
            nullptr, nullptr, nullptr, qkv, BT_, 3 * D_, D_, 0);
        attn_kernel<<<dim3(T_ / 128, B_ * H_), 256, ATTN_SMEM>>>(qkv, o);
        tgemm_kernel<<<dim3(4, MT), 128, GEMM_SMEM>>>(
            o, wproj + (size_t)l * D_ * D_,
            bproj + l * D_, x, x, nullptr, BT_, D_, D_, 3);
        ln_kernel<<<LNG, 256>>>(x, ln2_s + l * D_, ln2_b + l * D_, h);
        tgemm_kernel<<<dim3(16, MT), 128, GEMM_SMEM>>>(
            h, w1 + (size_t)l * FF_ * D_,
            b1 + l * FF_, nullptr, nullptr, ff, BT_, FF_, D_, 2);
        tgemm_kernel<<<dim3(4, MT), 128, GEMM_SMEM>>>(
            ff, w2 + (size_t)l * D_ * FF_,
            b2 + l * D_, x, x, nullptr, BT_, D_, FF_, 3);
    }

    ln_kernel<<<LNG, 256>>>(x, lnf_s, lnf_b, h);
    tgemm_kernel<<<dim3(1, MT), 128, GEMM_SMEM>>>(
        h, wout, bout, nullptr, out, nullptr, BT_, V_, D_, 1);

    if (out_size > BT_ * V_) {
        zero_loss_kernel<<<1, 1>>>(lossAcc);
        loss_kernel<<<BT_ / 8, 256>>>(out, targets, lossAcc);
        finalize_loss_kernel<<<1, 1>>>(out, lossAcc);
    }
}

// round 15
// speedup vs baseline: 1.1841x; 1.1841x over previous
#include <cuda_runtime.h>
#include <cuda_fp16.h>
#include <math.h>
#include <stdint.h>

// ---------------------------------------------------------------------------
// MiniTransformer forward: B=16, T=1024, D=512, H=8, HS=64, L=6, FF=2048, V=96
// Output: logits [16384, 96] (fp32) followed by scalar loss.
// GEMMs: fp16 m16n8k16, 64x32 warp tiles, 256-thread CTAs, BK=64 double buffer.
// Attention: fp16 mma flash attention, P kept in registers.
// ---------------------------------------------------------------------------

#define B_   16
#define T_   1024
#define D_   512
#define H_   8
#define HS_  64
#define L_   6
#define FF_  2048
#define V_   96
#define BT_  (B_ * T_)

// ------------------------- device scratch (no mallocs) ---------------------
__device__ float g_x   [BT_ * D_];          // residual stream (fp32)
__device__ half  g_h   [BT_ * D_];          // LN output (fp16)
__device__ half  g_qkv [BT_ * 3 * D_];      // q|k|v per token (fp16)
__device__ half  g_o   [BT_ * D_];          // attention output (fp16)
__device__ half  g_ff  [BT_ * FF_];         // FFN hidden (fp16)
// weights transposed to [n][k], fp16
__device__ half  g_wqkv [L_ * 3 * D_ * D_];
__device__ half  g_wproj[L_ * D_ * D_];
__device__ half  g_w1   [L_ * FF_ * D_];
__device__ half  g_w2   [L_ * D_ * FF_];
__device__ half  g_wout [V_ * D_];
__device__ double g_loss;

// ------------------------- helpers -----------------------------------------
__device__ __forceinline__ void cp16(uint32_t dst, const void* src, bool pred) {
    int sz = pred ? 16 : 0;
    asm volatile("cp.async.ca.shared.global [%0], [%1], 16, %2;\n"
                 :: "r"(dst), "l"(src), "r"(sz));
}
__device__ __forceinline__ void cp_commit() { asm volatile("cp.async.commit_group;\n"); }
__device__ __forceinline__ void cp_wait0()  { asm volatile("cp.async.wait_group 0;\n"); }

__device__ __forceinline__ void mma_f16(float* d, const uint32_t* a, const uint32_t* b) {
    asm volatile(
        "mma.sync.aligned.m16n8k16.row.col.f32.f16.f16.f32 "
        "{%0,%1,%2,%3}, {%4,%5,%6,%7}, {%8,%9}, {%0,%1,%2,%3};"
        : "+f"(d[0]), "+f"(d[1]), "+f"(d[2]), "+f"(d[3])
        : "r"(a[0]), "r"(a[1]), "r"(a[2]), "r"(a[3]), "r"(b[0]), "r"(b[1]));
}
__device__ __forceinline__ void ldsm_x4(uint32_t* r, uint32_t addr) {
    asm volatile("ldmatrix.sync.aligned.m8n8.x4.shared.b16 {%0,%1,%2,%3}, [%4];"
                 : "=r"(r[0]), "=r"(r[1]), "=r"(r[2]), "=r"(r[3]) : "r"(addr));
}
__device__ __forceinline__ void ldsm_x4_t(uint32_t* r, uint32_t addr) {
    asm volatile("ldmatrix.sync.aligned.m8n8.x4.trans.shared.b16 {%0,%1,%2,%3}, [%4];"
                 : "=r"(r[0]), "=r"(r[1]), "=r"(r[2]), "=r"(r[3]) : "r"(addr));
}

// ------------------------- small kernels -----------------------------------
__global__ void zero_loss_kernel(double* a) { *a = 0.0; }

// W [Lc][K][N] fp32 -> out [Lc][N][K] fp16, coalesced via 32x32 smem tiles.
__global__ void pack_wt_kernel(const float* __restrict__ W,
                               half* __restrict__ out, int K, int N) {
    __shared__ float tile[32][33];
    int l  = blockIdx.z;
    int n0 = blockIdx.x * 32, k0 = blockIdx.y * 32;
    int tx = threadIdx.x, ty = threadIdx.y;
    const float* Wl = W + (size_t)l * K * N;
    #pragma unroll
    for (int i = 0; i < 4; i++)
        tile[ty + i * 8][tx] = Wl[(size_t)(k0 + ty + i * 8) * N + n0 + tx];
    __syncthreads();
    half* ol = out + (size_t)l * N * K;
    #pragma unroll
    for (int i = 0; i < 4; i++)
        ol[(size_t)(n0 + ty + i * 8) * K + k0 + tx] = __float2half(tile[tx][ty + i * 8]);
}

// Wq/Wk/Wv [L][H][D][HS] -> packed transposed [L][3D(n)][D(k)] fp16.
__global__ void pack_qkv_kernel(const float* __restrict__ Wq,
                                const float* __restrict__ Wk,
                                const float* __restrict__ Wv,
                                half* __restrict__ out) {
    __shared__ float tile[32][33];
    int bz  = blockIdx.z;               // l*24 + sel*8 + h
    int h   = bz & 7;
    int sel = (bz >> 3) % 3;
    int l   = bz / 24;
    const float* W = (sel == 0) ? Wq : (sel == 1) ? Wk : Wv;
    const float* Wb = W + (((size_t)l * H_ + h) * D_) * HS_;
    int k0 = blockIdx.x * 32, hs0 = blockIdx.y * 32;
    int tx = threadIdx.x, ty = threadIdx.y;
    #pragma unroll
    for (int i = 0; i < 4; i++)
        tile[ty + i * 8][tx] = Wb[(size_t)(k0 + ty + i * 8) * HS_ + hs0 + tx];
    __syncthreads();
    #pragma unroll
    for (int i = 0; i < 4; i++) {
        int n = sel * 512 + h * 64 + hs0 + ty + i * 8;
        out[((size_t)l * 1536 + n) * D_ + k0 + tx] = __float2half(tile[tx][ty + i * 8]);
    }
}

__global__ void embed_kernel(const int* __restrict__ idx,
                             const float* __restrict__ tok,
                             const float* __restrict__ pos,
                             float* __restrict__ x) {
    int i = blockIdx.x * blockDim.x + threadIdx.x;
    if (i >= BT_ * D_) return;
    int d  = i & (D_ - 1);
    int bt = i >> 9;
    int t  = bt & (T_ - 1);
    x[i] = tok[(size_t)idx[bt] * D_ + d] + pos[t * D_ + d];
}

// warp-per-row LN: 8 rows per 256-thread block, 16 elems/lane, shfl-only.
__global__ __launch_bounds__(256) void ln_kernel(const float* __restrict__ x,
                                                 const float* __restrict__ s,
                                                 const float* __restrict__ b,
                                                 half* __restrict__ out) {
    int warp = threadIdx.x >> 5, lane = threadIdx.x & 31;
    size_t row = (size_t)blockIdx.x * 8 + warp;
    const float4* xr = (const float4*)(x + row * D_);

    float4 v[4];
    #pragma unroll
    for (int i = 0; i < 4; i++) v[i] = xr[lane * 4 + i];

    float sum = 0.f;
    #pragma unroll
    for (int i = 0; i < 4; i++) sum += v[i].x + v[i].y + v[i].z + v[i].w;
    #pragma unroll
    for (int o = 16; o; o >>= 1) sum += __shfl_xor_sync(0xffffffffu, sum, o);
    float mean = sum * (1.0f / D_);

    float vs = 0.f;
    #pragma unroll
    for (int i = 0; i < 4; i++) {
        float dx = v[i].x - mean, dy = v[i].y - mean;
        float dz = v[i].z - mean, dw = v[i].w - mean;
        vs += dx * dx + dy * dy + dz * dz + dw * dw;
    }
    #pragma unroll
    for (int o = 16; o; o >>= 1) vs += __shfl_xor_sync(0xffffffffu, vs, o);
    float inv = rsqrtf(vs * (1.0f / D_) + 1e-5f);

    const float4* sp = (const float4*)s;
    const float4* bp = (const float4*)b;
    half2 h2[8];
    #pragma unroll
    for (int i = 0; i < 4; i++) {
        float4 sv = sp[lane * 4 + i];
        float4 bv = bp[lane * 4 + i];
        float y0 = (v[i].x - mean) * inv * sv.x + bv.x;
        float y1 = (v[i].y - mean) * inv * sv.y + bv.y;
        float y2 = (v[i].z - mean) * inv * sv.z + bv.z;
        float y3 = (v[i].w - mean) * inv * sv.w + bv.w;
        h2[2 * i + 0] = __floats2half2_rn(y0, y1);
        h2[2 * i + 1] = __floats2half2_rn(y2, y3);
    }
    uint4* orow = (uint4*)(out + row * D_ + lane * 16);
    orow[0] = *(uint4*)&h2[0];
    orow[1] = *(uint4*)&h2[4];
}

// ------------------------- FP16 tensor-core GEMM ---------------------------
// C[M,N] = A[M,K] * B^T[N,K]   (A [m][k] fp16, B [n][k] fp16)
// mode: 0 = fp16 store (QKV); 1 = +bias fp32 (logits);
//       2 = +bias relu fp16 (FF1); 3 = +bias +residual fp32 (proj, FF2)
// 128x128 CTA tile, 256 threads = 8 warps, warp tile 64(m) x 32(n), BK=64.
// smem rows 72 halves (144B, ldmatrix conflict-free); 2-stage double buffer.
#define BK2 64
#define GROWB 144                // row stride bytes
#define GBUFB (128 * GROWB)      // one buffer (one array) bytes = 18432
#define GEMM_SMEM (4 * GBUFB)    // 2 stages x (A + B) = 73728

__global__ __launch_bounds__(256, 2) void tgemm_kernel(
    const half* __restrict__ A, const half* __restrict__ Bm,
    const float* __restrict__ bias, const float* __restrict__ res,
    float* __restrict__ Cf, half* __restrict__ Ch,
    int M, int N, int K, int mode)
{
    extern __shared__ __align__(16) half smg[];
    uint32_t smBase = (uint32_t)__cvta_generic_to_shared(smg);
    const uint32_t BOFF = 2 * GBUFB;

    int tid  = threadIdx.x;
    int wid  = tid >> 5;
    int lane = tid & 31;
    int grp  = lane >> 2;
    int tig  = lane & 3;
    int warp_m = (wid & 1) * 64;
    int warp_n = (wid >> 1) * 32;

    // loaders: row = tid>>1 (0..127), half-row sel = tid&1 (4 chunks of 16B each)
    int lrow = tid >> 1;
    int lhs  = tid & 1;

    const half* Ap = A + (size_t)(blockIdx.y * 128 + lrow) * K + lhs * 32;
    int gn = blockIdx.x * 128 + lrow;
    bool bp = gn < N;
    const half* Bp = Bm + (size_t)(bp ? gn : 0) * K + lhs * 32;
    uint32_t aDst = smBase + lrow * GROWB + lhs * 64;
    uint32_t bDst = smBase + BOFF + lrow * GROWB + lhs * 64;

    // ldmatrix fragment bases (buffer 0)
    uint32_t aLd = smBase + (warp_m + (lane & 7) + ((lane >> 3) & 1) * 8) * GROWB
                 + (lane >> 4) * 16;
    uint32_t bLd = smBase + BOFF + (warp_n + (lane & 7) + (lane >> 4) * 8) * GROWB
                 + ((lane >> 3) & 1) * 16;

    float acc[4][4][4];
    #pragma unroll
    for (int i = 0; i < 4; i++)
        #pragma unroll
        for (int j = 0; j < 4; j++)
            #pragma unroll
            for (int r = 0; r < 4; r++) acc[i][j][r] = 0.f;

    int nstage = K / BK2;

    // prologue: stage 0 -> buffer 0
    #pragma unroll
    for (int c = 0; c < 4; c++) {
        cp16(aDst + c * 16, Ap + c * 8, true);
        cp16(bDst + c * 16, Bp + c * 8, bp);
    }
    cp_commit();
    cp_wait0();
    __syncthreads();

    int cur = 0;
    for (int s = 0; s < nstage; s++) {
        if (s + 1 < nstage) {
            int k0 = (s + 1) * BK2;
            uint32_t io = (cur ^ 1) * GBUFB;
            #pragma unroll
            for (int c = 0; c < 4; c++) {
                cp16(aDst + io + c * 16, Ap + k0 + c * 8, true);
                cp16(bDst + io + c * 16, Bp + k0 + c * 8, bp);
            }
            cp_commit();
        }

        uint32_t bo = cur * GBUFB;
        #pragma unroll
        for (int ks = 0; ks < 4; ks++) {
            uint32_t af[4][4];
            #pragma unroll
            for (int i = 0; i < 4; i++)
                ldsm_x4(af[i], aLd + bo + i * (16 * GROWB) + ks * 32);
            uint32_t bq[2][4];
            #pragma unroll
            for (int jb = 0; jb < 2; jb++)
                ldsm_x4(bq[jb], bLd + bo + jb * (16 * GROWB) + ks * 32);
            #pragma unroll
            for (int i = 0; i < 4; i++)
                #pragma unroll
                for (int j = 0; j < 4; j++)
                    mma_f16(acc[i][j], af[i], &bq[j >> 1][2 * (j & 1)]);
        }

        if (s + 1 < nstage) {
            cp_wait0();
            __syncthreads();
            cur ^= 1;
        }
    }

    #pragma unroll
    for (int i = 0; i < 4; i++) {
        int row0 = blockIdx.y * 128 + warp_m + i * 16 + grp;
        #pragma unroll
        for (int j = 0; j < 4; j++) {
            int col = blockIdx.x * 128 + warp_n + j * 8 + 2 * tig;
            if (col < N) {
                #pragma unroll
                for (int hf = 0; hf < 2; hf++) {
                    int r = row0 + hf * 8;
                    size_t rb = (size_t)r * N;
                    float v0 = acc[i][j][hf * 2 + 0];
                    float v1 = acc[i][j][hf * 2 + 1];
                    if (mode >= 1) { v0 += bias[col]; v1 += bias[col + 1]; }
                    if (mode == 2) { v0 = fmaxf(v0, 0.f); v1 = fmaxf(v1, 0.f); }
                    if (mode == 0 || mode == 2) {
                        *(half2*)(Ch + rb + col) = __floats2half2_rn(v0, v1);
                    } else {
                        if (mode == 3) { v0 += res[rb + col]; v1 += res[rb + col + 1]; }
                        *(float2*)(Cf + rb + col) = make_float2(v0, v1);
                    }
                }
            }
        }
    }
}

// ------------------------- fp16 flash attention (P in registers) -----------
// 128 queries/block, 8 warps x 16 query-rows, 64-key tiles double-buffered.
#define KROWB 144
#define KVBUF (64 * KROWB)            // 9216
#define ATTN_SMEM (4 * KVBUF)         // 36864

__global__ __launch_bounds__(256, 2) void attn_kernel(const half* __restrict__ QKV,
                                                      half* __restrict__ O) {
    extern __shared__ __align__(16) half sma[];
    uint32_t smBase = (uint32_t)__cvta_generic_to_shared(sma);

    int b = blockIdx.y >> 3, h = blockIdx.y & 7;
    int qb = blockIdx.x * 128;
    int tid = threadIdx.x, wid = tid >> 5, lane = tid & 31;
    int grp = lane >> 2, tig = lane & 3;
    const float scale2 = 0.04419417382415922f * 1.4426950408889634f;

    int lr0 = wid * 16 + grp;
    int lr1 = lr0 + 8;
    int gr0 = qb + lr0, gr1 = qb + lr1;

    const half* q0p = QKV + ((size_t)(b * T_) + gr0) * 1536 + h * 64;
    const half* q1p = QKV + ((size_t)(b * T_) + gr1) * 1536 + h * 64;
    uint32_t qa[4][4];
    #pragma unroll
    for (int k = 0; k < 4; k++) {
        int dd = 16 * k + 2 * tig;
        #pragma unroll
        for (int r = 0; r < 4; r++) {
            const half* qp = (r & 1) ? q1p : q0p;
            int d2 = dd + (r >> 1) * 8;
            float2 f = __half22float2(*(const half2*)(qp + d2));
            half2 hv = __floats2half2_rn(f.x * scale2, f.y * scale2);
            qa[k][r] = *(uint32_t*)&hv;
        }
    }

    uint32_t kLd = smBase + ((lane & 7) + (lane >> 4) * 8) * KROWB
                 + ((lane >> 3) & 1) * 16;
    uint32_t vLd = smBase + 2 * KVBUF + ((lane & 7) + ((lane >> 3) & 1) * 8) * KROWB
                 + (lane >> 4) * 16;

    int key4 = tid >> 2, c4 = tid & 3;
    int dh = 8 * c4;
    uint32_t kDst = smBase + key4 * KROWB + dh * 2;
    uint32_t vDst = kDst + 2 * KVBUF;
    const half* kvb = QKV + (size_t)(b * T_) * 1536 + h * 64 + D_;
    const half* kRow = kvb + (size_t)key4 * 1536 + dh;

    float o[8][4];
    #pragma unroll
    for (int j = 0; j < 8; j++) { o[j][0] = o[j][1] = o[j][2] = o[j][3] = 0.f; }
    float m0 = -1e30f, m1 = -1e30f, l0 = 0.f, l1 = 0.f;

    int ntiles = (qb >> 6) + 2;

    {
        cp16(kDst,      kRow,        true);
        cp16(kDst + 64, kRow + 32,   true);
        cp16(vDst,      kRow + 512,  true);
        cp16(vDst + 64, kRow + 544,  true);
        cp_commit();
    }

    for (int t = 0; t < ntiles; t++) {
        cp_wait0();
        __syncthreads();

        if (t + 1 < ntiles) {
            uint32_t io = ((t + 1) & 1) * KVBUF;
            const half* kr = kRow + (size_t)(t + 1) * 64 * 1536;
            cp16(kDst + io,      kr,       true);
            cp16(kDst + io + 64, kr + 32,  true);
            cp16(vDst + io,      kr + 512, true);
            cp16(vDst + io + 64, kr + 544, true);
            cp_commit();
        }

        uint32_t bo = (t & 1) * KVBUF;
        int k0 = t * 64;

        float sc[8][4];
        #pragma unroll
        for (int j = 0; j < 8; j++) { sc[j][0] = sc[j][1] = sc[j][2] = sc[j][3] = 0.f; }
        #pragma unroll
        for (int kd = 0; kd < 4; kd++) {
            uint32_t kq[4][4];
            #pragma unroll
            for (int jp = 0; jp < 4; jp++)
                ldsm_x4(kq[jp], kLd + bo + jp * (16 * KROWB) + kd * 32);
            #pragma unroll
            for (int j = 0; j < 8; j++)
                mma_f16(sc[j], qa[kd], &kq[j >> 1][2 * (j & 1)]);
        }

        if (k0 + 63 > qb + wid * 16) {
            #pragma unroll
            for (int j = 0; j < 8; j++) {
                int key = k0 + 8 * j + 2 * tig;
                if (key     > gr0) sc[j][0] = -1e30f;
                if (key + 1 > gr0) sc[j][1] = -1e30f;
                if (key     > gr1) sc[j][2] = -1e30f;
                if (key + 1 > gr1) sc[j][3] = -1e30f;
            }
        }

        float mx0 = -1e30f, mx1 = -1e30f;
        #pragma unroll
        for (int j = 0; j < 8; j++) {
            mx0 = fmaxf(mx0, fmaxf(sc[j][0], sc[j][1]));
            mx1 = fmaxf(mx1, fmaxf(sc[j][2], sc[j][3]));
        }
        mx0 = fmaxf(mx0, __shfl_xor_sync(0xffffffffu, mx0, 1));
        mx0 = fmaxf(mx0, __shfl_xor_sync(0xffffffffu, mx0, 2));
        mx1 = fmaxf(mx1, __shfl_xor_sync(0xffffffffu, mx1, 1));
        mx1 = fmaxf(mx1, __shfl_xor_sync(0xffffffffu, mx1, 2));
        float mn0 = fmaxf(m0, mx0), mn1 = fmaxf(m1, mx1);
        float c0 = exp2f(m0 - mn0), c1 = exp2f(m1 - mn1);
        m0 = mn0; m1 = mn1;

        uint32_t pf[4][4];
        float s0 = 0.f, s1 = 0.f;
        #pragma unroll
        for (int k = 0; k < 4; k++) {
            float p00 = exp2f(sc[2 * k][0] - m0);
            float p01 = exp2f(sc[2 * k][1] - m0);
            float p02 = exp2f(sc[2 * k][2] - m1);
            float p03 = exp2f(sc[2 * k][3] - m1);
            float p10 = exp2f(sc[2 * k + 1][0] - m0);
            float p11 = exp2f(sc[2 * k + 1][1] - m0);
            float p12 = exp2f(sc[2 * k + 1][2] - m1);
            float p13 = exp2f(sc[2 * k + 1][3] - m1);
            s0 += p00 + p01 + p10 + p11;
            s1 += p02 + p03 + p12 + p13;
            half2 h0 = __floats2half2_rn(p00, p01);
            half2 h1 = __floats2half2_rn(p02, p03);
            half2 h2 = __floats2half2_rn(p10, p11);
            half2 h3 = __floats2half2_rn(p12, p13);
            pf[k][0] = *(uint32_t*)&h0;
            pf[k][1] = *(uint32_t*)&h1;
            pf[k][2] = *(uint32_t*)&h2;
            pf[k][3] = *(uint32_t*)&h3;
        }
        s0 += __shfl_xor_sync(0xffffffffu, s0, 1);
        s0 += __shfl_xor_sync(0xffffffffu, s0, 2);
        s1 += __shfl_xor_sync(0xffffffffu, s1, 1);
        s1 += __shfl_xor_sync(0xffffffffu, s1, 2);
        l0 = l0 * c0 + s0;
        l1 = l1 * c1 + s1;
        #pragma unroll
        for (int j = 0; j < 8; j++) {
            o[j][0] *= c0; o[j][1] *= c0; o[j][2] *= c1; o[j][3] *= c1;
        }

        #pragma unroll
        for (int kd = 0; kd < 4; kd++) {
            uint32_t vq[4][4];
            #pragma unroll
            for (int jp = 0; jp < 4; jp++)
                ldsm_x4_t(vq[jp], vLd + bo + kd * (16 * KROWB) + jp * 32);
            #pragma unroll
            for (int j = 0; j < 8; j++)
                mma_f16(o[j], pf[kd], &vq[j >> 1][2 * (j & 1)]);
        }
    }

    float i0 = 1.f / l0, i1 = 1.f / l1;
    size_t ob0 = ((size_t)(b * T_) + gr0) * D_ + h * 64;
    size_t ob1 = ((size_t)(b * T_) + gr1) * D_ + h * 64;
    #pragma unroll
    for (int j = 0; j < 8; j++) {
        int c = 8 * j + 2 * tig;
        *(half2*)(O + ob0 + c) = __floats2half2_rn(o[j][0] * i0, o[j][1] * i0);
        *(half2*)(O + ob1 + c) = __floats2half2_rn(o[j][2] * i1, o[j][3] * i1);
    }
}

// ------------------------- loss --------------------------------------------
__global__ __launch_bounds__(256) void loss_kernel(const float* __restrict__ logits,
                                                   const int* __restrict__ targets,
                                                   double* __restrict__ acc) {
    int warp = (blockIdx.x * blockDim.x + threadIdx.x) >> 5;
    int lane = threadIdx.x & 31;
    const float* lr = logits + (size_t)warp * V_;
    float v0 = lr[lane], v1 = lr[lane + 32], v2 = lr[lane + 64];
    float m = fmaxf(v0, fmaxf(v1, v2));
    #pragma unroll
    for (int o = 16; o; o >>= 1) m = fmaxf(m, __shfl_xor_sync(0xffffffffu, m, o));
    float se = expf(v0 - m) + expf(v1 - m) + expf(v2 - m);
    #pragma unroll
    for (int o = 16; o; o >>= 1) se += __shfl_xor_sync(0xffffffffu, se, o);

    __shared__ float part[8];
    if (lane == 0) part[threadIdx.x >> 5] = lr[targets[warp]] - m - logf(se);
    __syncthreads();
    if (threadIdx.x == 0) {
        float s = 0.f;
        #pragma unroll
        for (int i = 0; i < 8; i++) s += part[i];
        atomicAdd(acc, (double)s);
    }
}

__global__ void finalize_loss_kernel(float* out, const double* acc) {
    out[(size_t)BT_ * V_] = (float)(-(*acc) / (double)BT_);
}

// ------------------------- launcher ----------------------------------------
extern "C" void kernel_launch(void* const* d_in, const int* in_sizes, int n_in,
                              void* d_out, int out_size) {
    const int*   idx     = (const int*)  d_in[0];
    const int*   targets = (const int*)  d_in[1];
    const float* tok     = (const float*)d_in[2];
    const float* pos     = (const float*)d_in[3];
    const float* Wq      = (const float*)d_in[4];
    const float* Wk      = (const float*)d_in[5];
    const float* Wv      = (const float*)d_in[6];
    const float* Wproj   = (const float*)d_in[7];
    const float* bproj   = (const float*)d_in[8];
    const float* W1      = (const float*)d_in[9];
    const float* b1      = (const float*)d_in[10];
    const float* W2      = (const float*)d_in[11];
    const float* b2      = (const float*)d_in[12];
    const float* ln1_s   = (const float*)d_in[13];
    const float* ln1_b   = (const float*)d_in[14];
    const float* ln2_s   = (const float*)d_in[15];
    const float* ln2_b   = (const float*)d_in[16];
    const float* lnf_s   = (const float*)d_in[17];
    const float* lnf_b   = (const float*)d_in[18];
    const float* Wout    = (const float*)d_in[19];
    const float* bout    = (const float*)d_in[20];
    float* out = (float*)d_out;

    float* x;
    half *h, *qkv, *o, *ff, *wqkv, *wproj, *w1, *w2, *wout;
    double* lossAcc;
    cudaGetSymbolAddress((void**)&x,    g_x);
    cudaGetSymbolAddress((void**)&qkv,  g_qkv);
    cudaGetSymbolAddress((void**)&h,    g_h);
    cudaGetSymbolAddress((void**)&o,    g_o);
    cudaGetSymbolAddress((void**)&ff,   g_ff);
    cudaGetSymbolAddress((void**)&wqkv, g_wqkv);
    cudaGetSymbolAddress((void**)&wproj, g_wproj);
    cudaGetSymbolAddress((void**)&w1,   g_w1);
    cudaGetSymbolAddress((void**)&w2,   g_w2);
    cudaGetSymbolAddress((void**)&wout, g_wout);
    cudaGetSymbolAddress((void**)&lossAcc, g_loss);

    cudaFuncSetAttribute(tgemm_kernel,
                         cudaFuncAttributeMaxDynamicSharedMemorySize, GEMM_SMEM);
    cudaFuncSetAttribute(attn_kernel,
                         cudaFuncAttributeMaxDynamicSharedMemorySize, ATTN_SMEM);

    // weight packing (coalesced transposes, fp16)
    {
        dim3 blk(32, 8);
        pack_qkv_kernel<<<dim3(D_ / 32, HS_ / 32, L_ * 3 * H_), blk>>>(Wq, Wk, Wv, wqkv);
        pack_wt_kernel<<<dim3(D_ / 32, D_ / 32, L_), blk>>>(Wproj, wproj, D_, D_);
        pack_wt_kernel<<<dim3(FF_ / 32, D_ / 32, L_), blk>>>(W1, w1, D_, FF_);
        pack_wt_kernel<<<dim3(D_ / 32, FF_ / 32, L_), blk>>>(W2, w2, FF_, D_);
        pack_wt_kernel<<<dim3(V_ / 32, D_ / 32, 1), blk>>>(Wout, wout, D_, V_);
    }
    {
        int total = BT_ * D_;
        embed_kernel<<<(total + 255) / 256, 256>>>(idx, tok, pos, x);
    }

    const int MT = BT_ / 128;  // 128 M-tiles
    const int LNG = BT_ / 8;   // LN grid (8 rows/block)
    for (int l = 0; l < L_; l++) {
        ln_kernel<<<LNG, 256>>>(x, ln1_s + l * D_, ln1_b + l * D_, h);
        tgemm_kernel<<<dim3(12, MT), 256, GEMM_SMEM>>>(
            h, wqkv + (size_t)l * 3 * D_ * D_,
            nullptr, nullptr, nullptr, qkv, BT_, 3 * D_, D_, 0);
        attn_kernel<<<dim3(T_ / 128, B_ * H_), 256, ATTN_SMEM>>>(qkv, o);
        tgemm_kernel<<<dim3(4, MT), 256, GEMM_SMEM>>>(
            o, wproj + (size_t)l * D_ * D_,
            bproj + l * D_, x, x, nullptr, BT_, D_, D_, 3);
        ln_kernel<<<LNG, 256>>>(x, ln2_s + l * D_, ln2_b + l * D_, h);
        tgemm_kernel<<<dim3(16, MT), 256, GEMM_SMEM>>>(
            h, w1 + (size_t)l * FF_ * D_,
            b1 + l * FF_, nullptr, nullptr, ff, BT_, FF_, D_, 2);
        tgemm_kernel<<<dim3(4, MT), 256, GEMM_SMEM>>>(
            ff, w2 + (size_t)l * D_ * FF_,
            b2 + l * D_, x, x, nullptr, BT_, D_, FF_, 3);
    }

    ln_kernel<<<LNG, 256>>>(x, lnf_s, lnf_b, h);
    tgemm_kernel<<<dim3(1, MT), 256, GEMM_SMEM>>>(
        h, wout, bout, nullptr, out, nullptr, BT_, V_, D_, 1);

    if (out_size > BT_ * V_) {
        zero_loss_kernel<<<1, 1>>>(lossAcc);
        loss_kernel<<<BT_ / 8, 256>>>(out, targets, lossAcc);
        finalize_loss_kernel<<<1, 1>>>(out, lossAcc);
    }
}

// round 16
// speedup vs baseline: 1.3057x; 1.1027x over previous
#include <cuda_runtime.h>
#include <cuda_fp16.h>
#include <math.h>
#include <stdint.h>

// ---------------------------------------------------------------------------
// MiniTransformer forward: B=16, T=1024, D=512, H=8, HS=64, L=6, FF=2048, V=96
// Output: logits [16384, 96] (fp32) followed by scalar loss.
// GEMMs: fp16 m16n8k16, 64x32 warp tiles, 256-thread CTAs, BK=32 (R13 config).
// Attention: fp16 mma flash attention, P in registers, heavy-blocks-first.
// ---------------------------------------------------------------------------

#define B_   16
#define T_   1024
#define D_   512
#define H_   8
#define HS_  64
#define L_   6
#define FF_  2048
#define V_   96
#define BT_  (B_ * T_)

// ------------------------- device scratch (no mallocs) ---------------------
__device__ float g_x   [BT_ * D_];          // residual stream (fp32)
__device__ half  g_h   [BT_ * D_];          // LN output (fp16)
__device__ half  g_qkv [BT_ * 3 * D_];      // q|k|v per token (fp16)
__device__ half  g_o   [BT_ * D_];          // attention output (fp16)
__device__ half  g_ff  [BT_ * FF_];         // FFN hidden (fp16)
// weights transposed to [n][k], fp16
__device__ half  g_wqkv [L_ * 3 * D_ * D_];
__device__ half  g_wproj[L_ * D_ * D_];
__device__ half  g_w1   [L_ * FF_ * D_];
__device__ half  g_w2   [L_ * D_ * FF_];
__device__ half  g_wout [V_ * D_];
__device__ double g_loss;

// ------------------------- helpers -----------------------------------------
__device__ __forceinline__ void cp16(uint32_t dst, const void* src, bool pred) {
    int sz = pred ? 16 : 0;
    asm volatile("cp.async.ca.shared.global [%0], [%1], 16, %2;\n"
                 :: "r"(dst), "l"(src), "r"(sz));
}
__device__ __forceinline__ void cp_commit() { asm volatile("cp.async.commit_group;\n"); }
__device__ __forceinline__ void cp_wait0()  { asm volatile("cp.async.wait_group 0;\n"); }

__device__ __forceinline__ void mma_f16(float* d, const uint32_t* a, const uint32_t* b) {
    asm volatile(
        "mma.sync.aligned.m16n8k16.row.col.f32.f16.f16.f32 "
        "{%0,%1,%2,%3}, {%4,%5,%6,%7}, {%8,%9}, {%0,%1,%2,%3};"
        : "+f"(d[0]), "+f"(d[1]), "+f"(d[2]), "+f"(d[3])
        : "r"(a[0]), "r"(a[1]), "r"(a[2]), "r"(a[3]), "r"(b[0]), "r"(b[1]));
}
__device__ __forceinline__ void ldsm_x4(uint32_t* r, uint32_t addr) {
    asm volatile("ldmatrix.sync.aligned.m8n8.x4.shared.b16 {%0,%1,%2,%3}, [%4];"
                 : "=r"(r[0]), "=r"(r[1]), "=r"(r[2]), "=r"(r[3]) : "r"(addr));
}
__device__ __forceinline__ void ldsm_x4_t(uint32_t* r, uint32_t addr) {
    asm volatile("ldmatrix.sync.aligned.m8n8.x4.trans.shared.b16 {%0,%1,%2,%3}, [%4];"
                 : "=r"(r[0]), "=r"(r[1]), "=r"(r[2]), "=r"(r[3]) : "r"(addr));
}

// ------------------------- small kernels -----------------------------------
__global__ void zero_loss_kernel(double* a) { *a = 0.0; }

// W [Lc][K][N] fp32 -> out [Lc][N][K] fp16, coalesced via 32x32 smem tiles.
__global__ void pack_wt_kernel(const float* __restrict__ W,
                               half* __restrict__ out, int K, int N) {
    __shared__ float tile[32][33];
    int l  = blockIdx.z;
    int n0 = blockIdx.x * 32, k0 = blockIdx.y * 32;
    int tx = threadIdx.x, ty = threadIdx.y;
    const float* Wl = W + (size_t)l * K * N;
    #pragma unroll
    for (int i = 0; i < 4; i++)
        tile[ty + i * 8][tx] = Wl[(size_t)(k0 + ty + i * 8) * N + n0 + tx];
    __syncthreads();
    half* ol = out + (size_t)l * N * K;
    #pragma unroll
    for (int i = 0; i < 4; i++)
        ol[(size_t)(n0 + ty + i * 8) * K + k0 + tx] = __float2half(tile[tx][ty + i * 8]);
}

// Wq/Wk/Wv [L][H][D][HS] -> packed transposed [L][3D(n)][D(k)] fp16.
__global__ void pack_qkv_kernel(const float* __restrict__ Wq,
                                const float* __restrict__ Wk,
                                const float* __restrict__ Wv,
                                half* __restrict__ out) {
    __shared__ float tile[32][33];
    int bz  = blockIdx.z;               // l*24 + sel*8 + h
    int h   = bz & 7;
    int sel = (bz >> 3) % 3;
    int l   = bz / 24;
    const float* W = (sel == 0) ? Wq : (sel == 1) ? Wk : Wv;
    const float* Wb = W + (((size_t)l * H_ + h) * D_) * HS_;
    int k0 = blockIdx.x * 32, hs0 = blockIdx.y * 32;
    int tx = threadIdx.x, ty = threadIdx.y;
    #pragma unroll
    for (int i = 0; i < 4; i++)
        tile[ty + i * 8][tx] = Wb[(size_t)(k0 + ty + i * 8) * HS_ + hs0 + tx];
    __syncthreads();
    #pragma unroll
    for (int i = 0; i < 4; i++) {
        int n = sel * 512 + h * 64 + hs0 + ty + i * 8;
        out[((size_t)l * 1536 + n) * D_ + k0 + tx] = __float2half(tile[tx][ty + i * 8]);
    }
}

__global__ void embed_kernel(const int* __restrict__ idx,
                             const float* __restrict__ tok,
                             const float* __restrict__ pos,
                             float* __restrict__ x) {
    int i = blockIdx.x * blockDim.x + threadIdx.x;
    if (i >= BT_ * D_) return;
    int d  = i & (D_ - 1);
    int bt = i >> 9;
    int t  = bt & (T_ - 1);
    x[i] = tok[(size_t)idx[bt] * D_ + d] + pos[t * D_ + d];
}

// warp-per-row LN: 8 rows per 256-thread block, 16 elems/lane, shfl-only.
__global__ __launch_bounds__(256) void ln_kernel(const float* __restrict__ x,
                                                 const float* __restrict__ s,
                                                 const float* __restrict__ b,
                                                 half* __restrict__ out) {
    int warp = threadIdx.x >> 5, lane = threadIdx.x & 31;
    size_t row = (size_t)blockIdx.x * 8 + warp;
    const float4* xr = (const float4*)(x + row * D_);

    float4 v[4];
    #pragma unroll
    for (int i = 0; i < 4; i++) v[i] = xr[lane * 4 + i];

    float sum = 0.f;
    #pragma unroll
    for (int i = 0; i < 4; i++) sum += v[i].x + v[i].y + v[i].z + v[i].w;
    #pragma unroll
    for (int o = 16; o; o >>= 1) sum += __shfl_xor_sync(0xffffffffu, sum, o);
    float mean = sum * (1.0f / D_);

    float vs = 0.f;
    #pragma unroll
    for (int i = 0; i < 4; i++) {
        float dx = v[i].x - mean, dy = v[i].y - mean;
        float dz = v[i].z - mean, dw = v[i].w - mean;
        vs += dx * dx + dy * dy + dz * dz + dw * dw;
    }
    #pragma unroll
    for (int o = 16; o; o >>= 1) vs += __shfl_xor_sync(0xffffffffu, vs, o);
    float inv = rsqrtf(vs * (1.0f / D_) + 1e-5f);

    const float4* sp = (const float4*)s;
    const float4* bp = (const float4*)b;
    half2 h2[8];
    #pragma unroll
    for (int i = 0; i < 4; i++) {
        float4 sv = sp[lane * 4 + i];
        float4 bv = bp[lane * 4 + i];
        float y0 = (v[i].x - mean) * inv * sv.x + bv.x;
        float y1 = (v[i].y - mean) * inv * sv.y + bv.y;
        float y2 = (v[i].z - mean) * inv * sv.z + bv.z;
        float y3 = (v[i].w - mean) * inv * sv.w + bv.w;
        h2[2 * i + 0] = __floats2half2_rn(y0, y1);
        h2[2 * i + 1] = __floats2half2_rn(y2, y3);
    }
    uint4* orow = (uint4*)(out + row * D_ + lane * 16);
    orow[0] = *(uint4*)&h2[0];
    orow[1] = *(uint4*)&h2[4];
}

// ------------------------- FP16 tensor-core GEMM (R13 config) --------------
// C[M,N] = A[M,K] * B^T[N,K]   (A [m][k] fp16, B [n][k] fp16)
// mode: 0 = fp16 store (QKV); 1 = +bias fp32 (logits);
//       2 = +bias relu fp16 (FF1); 3 = +bias +residual fp32 (proj, FF2)
// 128x128 CTA tile, 256 threads = 8 warps, warp tile 64(m) x 32(n), BK=32.
#define BK2 32
#define GROWB 80                 // row stride bytes
#define GBUFB (128 * 80)         // one buffer (one array) bytes = 10240
#define GEMM_SMEM (4 * GBUFB)    // 2 stages x (A + B) = 40960

__global__ __launch_bounds__(256, 2) void tgemm_kernel(
    const half* __restrict__ A, const half* __restrict__ Bm,
    const float* __restrict__ bias, const float* __restrict__ res,
    float* __restrict__ Cf, half* __restrict__ Ch,
    int M, int N, int K, int mode)
{
    extern __shared__ __align__(16) half smg[];
    uint32_t smBase = (uint32_t)__cvta_generic_to_shared(smg);
    const uint32_t BOFF = 2 * GBUFB;

    int tid  = threadIdx.x;
    int wid  = tid >> 5;
    int lane = tid & 31;
    int grp  = lane >> 2;
    int tig  = lane & 3;
    int warp_m = (wid & 1) * 64;
    int warp_n = (wid >> 1) * 32;

    int lrow = tid >> 2;
    int lc   = tid & 3;

    const half* Ap  = A + (size_t)(blockIdx.y * 128 + lrow) * K + lc * 8;
    const half* Ap2 = Ap + (size_t)64 * K;
    int gn  = blockIdx.x * 128 + lrow;
    int gn2 = gn + 64;
    bool bp  = gn  < N;
    bool bp2 = gn2 < N;
    const half* Bp  = Bm + (size_t)(bp  ? gn  : 0) * K + lc * 8;
    const half* Bp2 = Bm + (size_t)(bp2 ? gn2 : 0) * K + lc * 8;

    uint32_t aDst  = smBase + lrow * GROWB + lc * 16;
    uint32_t aDst2 = aDst + 64 * GROWB;
    uint32_t bDst  = smBase + BOFF + lrow * GROWB + lc * 16;
    uint32_t bDst2 = bDst + 64 * GROWB;

    uint32_t aLd = smBase + (warp_m + (lane & 7) + ((lane >> 3) & 1) * 8) * GROWB
                 + (lane >> 4) * 16;
    uint32_t bLd = smBase + BOFF + (warp_n + (lane & 7) + (lane >> 4) * 8) * GROWB
                 + ((lane >> 3) & 1) * 16;

    float acc[4][4][4];
    #pragma unroll
    for (int i = 0; i < 4; i++)
        #pragma unroll
        for (int j = 0; j < 4; j++)
            #pragma unroll
            for (int r = 0; r < 4; r++) acc[i][j][r] = 0.f;

    int nstage = K / BK2;

    // prologue: stage 0 -> buffer 0
    cp16(aDst, Ap, true);
    cp16(aDst2, Ap2, true);
    cp16(bDst, Bp, bp);
    cp16(bDst2, Bp2, bp2);
    cp_commit();
    cp_wait0();
    __syncthreads();

    int cur = 0;
    for (int s = 0; s < nstage; s++) {
        if (s + 1 < nstage) {
            int k0 = (s + 1) * BK2;
            uint32_t io = (cur ^ 1) * GBUFB;
            cp16(aDst + io, Ap + k0, true);
            cp16(aDst2 + io, Ap2 + k0, true);
            cp16(bDst + io, Bp + k0, bp);
            cp16(bDst2 + io, Bp2 + k0, bp2);
            cp_commit();
        }

        uint32_t bo = cur * GBUFB;
        #pragma unroll
        for (int ks = 0; ks < 2; ks++) {
            uint32_t af[4][4];
            #pragma unroll
            for (int i = 0; i < 4; i++)
                ldsm_x4(af[i], aLd + bo + i * (16 * GROWB) + ks * 32);
            uint32_t bq[2][4];
            #pragma unroll
            for (int jb = 0; jb < 2; jb++)
                ldsm_x4(bq[jb], bLd + bo + jb * (16 * GROWB) + ks * 32);
            #pragma unroll
            for (int i = 0; i < 4; i++)
                #pragma unroll
                for (int j = 0; j < 4; j++)
                    mma_f16(acc[i][j], af[i], &bq[j >> 1][2 * (j & 1)]);
        }

        if (s + 1 < nstage) {
            cp_wait0();
            __syncthreads();
            cur ^= 1;
        }
    }

    #pragma unroll
    for (int i = 0; i < 4; i++) {
        int row0 = blockIdx.y * 128 + warp_m + i * 16 + grp;
        #pragma unroll
        for (int j = 0; j < 4; j++) {
            int col = blockIdx.x * 128 + warp_n + j * 8 + 2 * tig;
            if (col < N) {
                #pragma unroll
                for (int hf = 0; hf < 2; hf++) {
                    int r = row0 + hf * 8;
                    size_t rb = (size_t)r * N;
                    float v0 = acc[i][j][hf * 2 + 0];
                    float v1 = acc[i][j][hf * 2 + 1];
                    if (mode >= 1) { v0 += bias[col]; v1 += bias[col + 1]; }
                    if (mode == 2) { v0 = fmaxf(v0, 0.f); v1 = fmaxf(v1, 0.f); }
                    if (mode == 0 || mode == 2) {
                        *(half2*)(Ch + rb + col) = __floats2half2_rn(v0, v1);
                    } else {
                        if (mode == 3) { v0 += res[rb + col]; v1 += res[rb + col + 1]; }
                        *(float2*)(Cf + rb + col) = make_float2(v0, v1);
                    }
                }
            }
        }
    }
}

// ------------------------- fp16 flash attention (P in registers) -----------
// 128 queries/block, 8 warps x 16 query-rows, 64-key tiles double-buffered.
// Heavy-blocks-first: qb descends with blockIdx.x so long blocks start early.
#define KROWB 144
#define KVBUF (64 * KROWB)            // 9216
#define ATTN_SMEM (4 * KVBUF)         // 36864

__global__ __launch_bounds__(256, 2) void attn_kernel(const half* __restrict__ QKV,
                                                      half* __restrict__ O) {
    extern __shared__ __align__(16) half sma[];
    uint32_t smBase = (uint32_t)__cvta_generic_to_shared(sma);

    int b = blockIdx.y >> 3, h = blockIdx.y & 7;
    int qb = (gridDim.x - 1 - blockIdx.x) * 128;   // heavy blocks first
    int tid = threadIdx.x, wid = tid >> 5, lane = tid & 31;
    int grp = lane >> 2, tig = lane & 3;
    const float scale2 = 0.04419417382415922f * 1.4426950408889634f;

    int lr0 = wid * 16 + grp;
    int lr1 = lr0 + 8;
    int gr0 = qb + lr0, gr1 = qb + lr1;

    const half* q0p = QKV + ((size_t)(b * T_) + gr0) * 1536 + h * 64;
    const half* q1p = QKV + ((size_t)(b * T_) + gr1) * 1536 + h * 64;
    uint32_t qa[4][4];
    #pragma unroll
    for (int k = 0; k < 4; k++) {
        int dd = 16 * k + 2 * tig;
        #pragma unroll
        for (int r = 0; r < 4; r++) {
            const half* qp = (r & 1) ? q1p : q0p;
            int d2 = dd + (r >> 1) * 8;
            float2 f = __half22float2(*(const half2*)(qp + d2));
            half2 hv = __floats2half2_rn(f.x * scale2, f.y * scale2);
            qa[k][r] = *(uint32_t*)&hv;
        }
    }

    uint32_t kLd = smBase + ((lane & 7) + (lane >> 4) * 8) * KROWB
                 + ((lane >> 3) & 1) * 16;
    uint32_t vLd = smBase + 2 * KVBUF + ((lane & 7) + ((lane >> 3) & 1) * 8) * KROWB
                 + (lane >> 4) * 16;

    int key4 = tid >> 2, c4 = tid & 3;
    int dh = 8 * c4;
    uint32_t kDst = smBase + key4 * KROWB + dh * 2;
    uint32_t vDst = kDst + 2 * KVBUF;
    const half* kvb = QKV + (size_t)(b * T_) * 1536 + h * 64 + D_;
    const half* kRow = kvb + (size_t)key4 * 1536 + dh;

    float o[8][4];
    #pragma unroll
    for (int j = 0; j < 8; j++) { o[j][0] = o[j][1] = o[j][2] = o[j][3] = 0.f; }
    float m0 = -1e30f, m1 = -1e30f, l0 = 0.f, l1 = 0.f;

    int ntiles = (qb >> 6) + 2;

    {
        cp16(kDst,      kRow,        true);
        cp16(kDst + 64, kRow + 32,   true);
        cp16(vDst,      kRow + 512,  true);
        cp16(vDst + 64, kRow + 544,  true);
        cp_commit();
    }

    for (int t = 0; t < ntiles; t++) {
        cp_wait0();
        __syncthreads();

        if (t + 1 < ntiles) {
            uint32_t io = ((t + 1) & 1) * KVBUF;
            const half* kr = kRow + (size_t)(t + 1) * 64 * 1536;
            cp16(kDst + io,      kr,       true);
            cp16(kDst + io + 64, kr + 32,  true);
            cp16(vDst + io,      kr + 512, true);
            cp16(vDst + io + 64, kr + 544, true);
            cp_commit();
        }

        uint32_t bo = (t & 1) * KVBUF;
        int k0 = t * 64;

        float sc[8][4];
        #pragma unroll
        for (int j = 0; j < 8; j++) { sc[j][0] = sc[j][1] = sc[j][2] = sc[j][3] = 0.f; }
        #pragma unroll
        for (int kd = 0; kd < 4; kd++) {
            uint32_t kq[4][4];
            #pragma unroll
            for (int jp = 0; jp < 4; jp++)
                ldsm_x4(kq[jp], kLd + bo + jp * (16 * KROWB) + kd * 32);
            #pragma unroll
            for (int j = 0; j < 8; j++)
                mma_f16(sc[j], qa[kd], &kq[j >> 1][2 * (j & 1)]);
        }

        if (k0 + 63 > qb + wid * 16) {
            #pragma unroll
            for (int j = 0; j < 8; j++) {
                int key = k0 + 8 * j + 2 * tig;
                if (key     > gr0) sc[j][0] = -1e30f;
                if (key + 1 > gr0) sc[j][1] = -1e30f;
                if (key     > gr1) sc[j][2] = -1e30f;
                if (key + 1 > gr1) sc[j][3] = -1e30f;
            }
        }

        float mx0 = -1e30f, mx1 = -1e30f;
        #pragma unroll
        for (int j = 0; j < 8; j++) {
            mx0 = fmaxf(mx0, fmaxf(sc[j][0], sc[j][1]));
            mx1 = fmaxf(mx1, fmaxf(sc[j][2], sc[j][3]));
        }
        mx0 = fmaxf(mx0, __shfl_xor_sync(0xffffffffu, mx0, 1));
        mx0 = fmaxf(mx0, __shfl_xor_sync(0xffffffffu, mx0, 2));
        mx1 = fmaxf(mx1, __shfl_xor_sync(0xffffffffu, mx1, 1));
        mx1 = fmaxf(mx1, __shfl_xor_sync(0xffffffffu, mx1, 2));
        float mn0 = fmaxf(m0, mx0), mn1 = fmaxf(m1, mx1);
        float c0 = exp2f(m0 - mn0), c1 = exp2f(m1 - mn1);
        m0 = mn0; m1 = mn1;

        uint32_t pf[4][4];
        float s0 = 0.f, s1 = 0.f;
        #pragma unroll
        for (int k = 0; k < 4; k++) {
            float p00 = exp2f(sc[2 * k][0] - m0);
            float p01 = exp2f(sc[2 * k][1] - m0);
            float p02 = exp2f(sc[2 * k][2] - m1);
            float p03 = exp2f(sc[2 * k][3] - m1);
            float p10 = exp2f(sc[2 * k + 1][0] - m0);
            float p11 = exp2f(sc[2 * k + 1][1] - m0);
            float p12 = exp2f(sc[2 * k + 1][2] - m1);
            float p13 = exp2f(sc[2 * k + 1][3] - m1);
            s0 += p00 + p01 + p10 + p11;
            s1 += p02 + p03 + p12 + p13;
            half2 h0 = __floats2half2_rn(p00, p01);
            half2 h1 = __floats2half2_rn(p02, p03);
            half2 h2 = __floats2half2_rn(p10, p11);
            half2 h3 = __floats2half2_rn(p12, p13);
            pf[k][0] = *(uint32_t*)&h0;
            pf[k][1] = *(uint32_t*)&h1;
            pf[k][2] = *(uint32_t*)&h2;
            pf[k][3] = *(uint32_t*)&h3;
        }
        s0 += __shfl_xor_sync(0xffffffffu, s0, 1);
        s0 += __shfl_xor_sync(0xffffffffu, s0, 2);
        s1 += __shfl_xor_sync(0xffffffffu, s1, 1);
        s1 += __shfl_xor_sync(0xffffffffu, s1, 2);
        l0 = l0 * c0 + s0;
        l1 = l1 * c1 + s1;
        #pragma unroll
        for (int j = 0; j < 8; j++) {
            o[j][0] *= c0; o[j][1] *= c0; o[j][2] *= c1; o[j][3] *= c1;
        }

        #pragma unroll
        for (int kd = 0; kd < 4; kd++) {
            uint32_t vq[4][4];
            #pragma unroll
            for (int jp = 0; jp < 4; jp++)
                ldsm_x4_t(vq[jp], vLd + bo + kd * (16 * KROWB) + jp * 32);
            #pragma unroll
            for (int j = 0; j < 8; j++)
                mma_f16(o[j], pf[kd], &vq[j >> 1][2 * (j & 1)]);
        }
    }

    float i0 = 1.f / l0, i1 = 1.f / l1;
    size_t ob0 = ((size_t)(b * T_) + gr0) * D_ + h * 64;
    size_t ob1 = ((size_t)(b * T_) + gr1) * D_ + h * 64;
    #pragma unroll
    for (int j = 0; j < 8; j++) {
        int c = 8 * j + 2 * tig;
        *(half2*)(O + ob0 + c) = __floats2half2_rn(o[j][0] * i0, o[j][1] * i0);
        *(half2*)(O + ob1 + c) = __floats2half2_rn(o[j][2] * i1, o[j][3] * i1);
    }
}

// ------------------------- loss --------------------------------------------
__global__ __launch_bounds__(256) void loss_kernel(const float* __restrict__ logits,
                                                   const int* __restrict__ targets,
                                                   double* __restrict__ acc) {
    int warp = (blockIdx.x * blockDim.x + threadIdx.x) >> 5;
    int lane = threadIdx.x & 31;
    const float* lr = logits + (size_t)warp * V_;
    float v0 = lr[lane], v1 = lr[lane + 32], v2 = lr[lane + 64];
    float m = fmaxf(v0, fmaxf(v1, v2));
    #pragma unroll
    for (int o = 16; o; o >>= 1) m = fmaxf(m, __shfl_xor_sync(0xffffffffu, m, o));
    float se = expf(v0 - m) + expf(v1 - m) + expf(v2 - m);
    #pragma unroll
    for (int o = 16; o; o >>= 1) se += __shfl_xor_sync(0xffffffffu, se, o);

    __shared__ float part[8];
    if (lane == 0) part[threadIdx.x >> 5] = lr[targets[warp]] - m - logf(se);
    __syncthreads();
    if (threadIdx.x == 0) {
        float s = 0.f;
        #pragma unroll
        for (int i = 0; i < 8; i++) s += part[i];
        atomicAdd(acc, (double)s);
    }
}

__global__ void finalize_loss_kernel(float* out, const double* acc) {
    out[(size_t)BT_ * V_] = (float)(-(*acc) / (double)BT_);
}

// ------------------------- launcher ----------------------------------------
extern "C" void kernel_launch(void* const* d_in, const int* in_sizes, int n_in,
                              void* d_out, int out_size) {
    const int*   idx     = (const int*)  d_in[0];
    const int*   targets = (const int*)  d_in[1];
    const float* tok     = (const float*)d_in[2];
    const float* pos     = (const float*)d_in[3];
    const float* Wq      = (const float*)d_in[4];
    const float* Wk      = (const float*)d_in[5];
    const float* Wv      = (const float*)d_in[6];
    const float* Wproj   = (const float*)d_in[7];
    const float* bproj   = (const float*)d_in[8];
    const float* W1      = (const float*)d_in[9];
    const float* b1      = (const float*)d_in[10];
    const float* W2      = (const float*)d_in[11];
    const float* b2      = (const float*)d_in[12];
    const float* ln1_s   = (const float*)d_in[13];
    const float* ln1_b   = (const float*)d_in[14];
    const float* ln2_s   = (const float*)d_in[15];
    const float* ln2_b   = (const float*)d_in[16];
    const float* lnf_s   = (const float*)d_in[17];
    const float* lnf_b   = (const float*)d_in[18];
    const float* Wout    = (const float*)d_in[19];
    const float* bout    = (const float*)d_in[20];
    float* out = (float*)d_out;

    float* x;
    half *h, *qkv, *o, *ff, *wqkv, *wproj, *w1, *w2, *wout;
    double* lossAcc;
    cudaGetSymbolAddress((void**)&x,    g_x);
    cudaGetSymbolAddress((void**)&qkv,  g_qkv);
    cudaGetSymbolAddress((void**)&h,    g_h);
    cudaGetSymbolAddress((void**)&o,    g_o);
    cudaGetSymbolAddress((void**)&ff,   g_ff);
    cudaGetSymbolAddress((void**)&wqkv, g_wqkv);
    cudaGetSymbolAddress((void**)&wproj, g_wproj);
    cudaGetSymbolAddress((void**)&w1,   g_w1);
    cudaGetSymbolAddress((void**)&w2,   g_w2);
    cudaGetSymbolAddress((void**)&wout, g_wout);
    cudaGetSymbolAddress((void**)&lossAcc, g_loss);

    cudaFuncSetAttribute(tgemm_kernel,
                         cudaFuncAttributeMaxDynamicSharedMemorySize, GEMM_SMEM);
    cudaFuncSetAttribute(attn_kernel,
                         cudaFuncAttributeMaxDynamicSharedMemorySize, ATTN_SMEM);

    // weight packing (coalesced transposes, fp16)
    {
        dim3 blk(32, 8);
        pack_qkv_kernel<<<dim3(D_ / 32, HS_ / 32, L_ * 3 * H_), blk>>>(Wq, Wk, Wv, wqkv);
        pack_wt_kernel<<<dim3(D_ / 32, D_ / 32, L_), blk>>>(Wproj, wproj, D_, D_);
        pack_wt_kernel<<<dim3(FF_ / 32, D_ / 32, L_), blk>>>(W1, w1, D_, FF_);
        pack_wt_kernel<<<dim3(D_ / 32, FF_ / 32, L_), blk>>>(W2, w2, FF_, D_);
        pack_wt_kernel<<<dim3(V_ / 32, D_ / 32, 1), blk>>>(Wout, wout, D_, V_);
    }
    {
        int total = BT_ * D_;
        embed_kernel<<<(total + 255) / 256, 256>>>(idx, tok, pos, x);
    }

    const int MT = BT_ / 128;  // 128 M-tiles
    const int LNG = BT_ / 8;   // LN grid (8 rows/block)
    for (int l = 0; l < L_; l++) {
        ln_kernel<<<LNG, 256>>>(x, ln1_s + l * D_, ln1_b + l * D_, h);
        tgemm_kernel<<<dim3(12, MT), 256, GEMM_SMEM>>>(
            h, wqkv + (size_t)l * 3 * D_ * D_,
            nullptr, nullptr, nullptr, qkv, BT_, 3 * D_, D_, 0);
        attn_kernel<<<dim3(T_ / 128, B_ * H_), 256, ATTN_SMEM>>>(qkv, o);
        tgemm_kernel<<<dim3(4, MT), 256, GEMM_SMEM>>>(
            o, wproj + (size_t)l * D_ * D_,
            bproj + l * D_, x, x, nullptr, BT_, D_, D_, 3);
        ln_kernel<<<LNG, 256>>>(x, ln2_s + l * D_, ln2_b + l * D_, h);
        tgemm_kernel<<<dim3(16, MT), 256, GEMM_SMEM>>>(
            h, w1 + (size_t)l * FF_ * D_,
            b1 + l * FF_, nullptr, nullptr, ff, BT_, FF_, D_, 2);
        tgemm_kernel<<<dim3(4, MT), 256, GEMM_SMEM>>>(
            ff, w2 + (size_t)l * D_ * FF_,
            b2 + l * D_, x, x, nullptr, BT_, D_, FF_, 3);
    }

    ln_kernel<<<LNG, 256>>>(x, lnf_s, lnf_b, h);
    tgemm_kernel<<<dim3(1, MT), 256, GEMM_SMEM>>>(
        h, wout, bout, nullptr, out, nullptr, BT_, V_, D_, 1);

    if (out_size > BT_ * V_) {
        zero_loss_kernel<<<1, 1>>>(lossAcc);
        loss_kernel<<<BT_ / 8, 256>>>(out, targets, lossAcc);
        finalize_loss_kernel<<<1, 1>>>(out, lossAcc);
    }
}

// round 17
// speedup vs baseline: 1.3061x; 1.0003x over previous
#include <cuda_runtime.h>
#include <cuda_fp16.h>
#include <math.h>
#include <stdint.h>

// ---------------------------------------------------------------------------
// MiniTransformer forward: B=16, T=1024, D=512, H=8, HS=64, L=6, FF=2048, V=96
// Output: logits [16384, 96] (fp32) followed by scalar loss.
// GEMMs: fp16 m16n8k16, 64x32 warp tiles, 256-thread CTAs, BK=32 (R13 config).
// Attention: fp16 mma flash attention, P in registers, MUFU ex2 softmax.
// ---------------------------------------------------------------------------

#define B_   16
#define T_   1024
#define D_   512
#define H_   8
#define HS_  64
#define L_   6
#define FF_  2048
#define V_   96
#define BT_  (B_ * T_)

// ------------------------- device scratch (no mallocs) ---------------------
__device__ float g_x   [BT_ * D_];          // residual stream (fp32)
__device__ half  g_h   [BT_ * D_];          // LN output (fp16)
__device__ half  g_qkv [BT_ * 3 * D_];      // q|k|v per token (fp16)
__device__ half  g_o   [BT_ * D_];          // attention output (fp16)
__device__ half  g_ff  [BT_ * FF_];         // FFN hidden (fp16)
// weights transposed to [n][k], fp16
__device__ half  g_wqkv [L_ * 3 * D_ * D_];
__device__ half  g_wproj[L_ * D_ * D_];
__device__ half  g_w1   [L_ * FF_ * D_];
__device__ half  g_w2   [L_ * D_ * FF_];
__device__ half  g_wout [V_ * D_];
__device__ double g_loss;

// ------------------------- helpers -----------------------------------------
__device__ __forceinline__ void cp16(uint32_t dst, const void* src, bool pred) {
    int sz = pred ? 16 : 0;
    asm volatile("cp.async.ca.shared.global [%0], [%1], 16, %2;\n"
                 :: "r"(dst), "l"(src), "r"(sz));
}
__device__ __forceinline__ void cp_commit() { asm volatile("cp.async.commit_group;\n"); }
__device__ __forceinline__ void cp_wait0()  { asm volatile("cp.async.wait_group 0;\n"); }

__device__ __forceinline__ void mma_f16(float* d, const uint32_t* a, const uint32_t* b) {
    asm volatile(
        "mma.sync.aligned.m16n8k16.row.col.f32.f16.f16.f32 "
        "{%0,%1,%2,%3}, {%4,%5,%6,%7}, {%8,%9}, {%0,%1,%2,%3};"
        : "+f"(d[0]), "+f"(d[1]), "+f"(d[2]), "+f"(d[3])
        : "r"(a[0]), "r"(a[1]), "r"(a[2]), "r"(a[3]), "r"(b[0]), "r"(b[1]));
}
__device__ __forceinline__ void ldsm_x4(uint32_t* r, uint32_t addr) {
    asm volatile("ldmatrix.sync.aligned.m8n8.x4.shared.b16 {%0,%1,%2,%3}, [%4];"
                 : "=r"(r[0]), "=r"(r[1]), "=r"(r[2]), "=r"(r[3]) : "r"(addr));
}
__device__ __forceinline__ void ldsm_x4_t(uint32_t* r, uint32_t addr) {
    asm volatile("ldmatrix.sync.aligned.m8n8.x4.trans.shared.b16 {%0,%1,%2,%3}, [%4];"
                 : "=r"(r[0]), "=r"(r[1]), "=r"(r[2]), "=r"(r[3]) : "r"(addr));
}
// raw MUFU.EX2 (exp2f without fast-math carries libdevice fixup code)
__device__ __forceinline__ float ex2(float x) {
    float y;
    asm("ex2.approx.f32 %0, %1;" : "=f"(y) : "f"(x));
    return y;
}

// ------------------------- small kernels -----------------------------------
__global__ void zero_loss_kernel(double* a) { *a = 0.0; }

// W [Lc][K][N] fp32 -> out [Lc][N][K] fp16, coalesced via 32x32 smem tiles.
__global__ void pack_wt_kernel(const float* __restrict__ W,
                               half* __restrict__ out, int K, int N) {
    __shared__ float tile[32][33];
    int l  = blockIdx.z;
    int n0 = blockIdx.x * 32, k0 = blockIdx.y * 32;
    int tx = threadIdx.x, ty = threadIdx.y;
    const float* Wl = W + (size_t)l * K * N;
    #pragma unroll
    for (int i = 0; i < 4; i++)
        tile[ty + i * 8][tx] = Wl[(size_t)(k0 + ty + i * 8) * N + n0 + tx];
    __syncthreads();
    half* ol = out + (size_t)l * N * K;
    #pragma unroll
    for (int i = 0; i < 4; i++)
        ol[(size_t)(n0 + ty + i * 8) * K + k0 + tx] = __float2half(tile[tx][ty + i * 8]);
}

// Wq/Wk/Wv [L][H][D][HS] -> packed transposed [L][3D(n)][D(k)] fp16.
__global__ void pack_qkv_kernel(const float* __restrict__ Wq,
                                const float* __restrict__ Wk,
                                const float* __restrict__ Wv,
                                half* __restrict__ out) {
    __shared__ float tile[32][33];
    int bz  = blockIdx.z;               // l*24 + sel*8 + h
    int h   = bz & 7;
    int sel = (bz >> 3) % 3;
    int l   = bz / 24;
    const float* W = (sel == 0) ? Wq : (sel == 1) ? Wk : Wv;
    const float* Wb = W + (((size_t)l * H_ + h) * D_) * HS_;
    int k0 = blockIdx.x * 32, hs0 = blockIdx.y * 32;
    int tx = threadIdx.x, ty = threadIdx.y;
    #pragma unroll
    for (int i = 0; i < 4; i++)
        tile[ty + i * 8][tx] = Wb[(size_t)(k0 + ty + i * 8) * HS_ + hs0 + tx];
    __syncthreads();
    #pragma unroll
    for (int i = 0; i < 4; i++) {
        int n = sel * 512 + h * 64 + hs0 + ty + i * 8;
        out[((size_t)l * 1536 + n) * D_ + k0 + tx] = __float2half(tile[tx][ty + i * 8]);
    }
}

__global__ void embed_kernel(const int* __restrict__ idx,
                             const float* __restrict__ tok,
                             const float* __restrict__ pos,
                             float* __restrict__ x) {
    int i = blockIdx.x * blockDim.x + threadIdx.x;
    if (i >= BT_ * D_) return;
    int d  = i & (D_ - 1);
    int bt = i >> 9;
    int t  = bt & (T_ - 1);
    x[i] = tok[(size_t)idx[bt] * D_ + d] + pos[t * D_ + d];
}

// warp-per-row LN: 8 rows per 256-thread block, 16 elems/lane, shfl-only.
__global__ __launch_bounds__(256) void ln_kernel(const float* __restrict__ x,
                                                 const float* __restrict__ s,
                                                 const float* __restrict__ b,
                                                 half* __restrict__ out) {
    int warp = threadIdx.x >> 5, lane = threadIdx.x & 31;
    size_t row = (size_t)blockIdx.x * 8 + warp;
    const float4* xr = (const float4*)(x + row * D_);

    float4 v[4];
    #pragma unroll
    for (int i = 0; i < 4; i++) v[i] = xr[lane * 4 + i];

    float sum = 0.f;
    #pragma unroll
    for (int i = 0; i < 4; i++) sum += v[i].x + v[i].y + v[i].z + v[i].w;
    #pragma unroll
    for (int o = 16; o; o >>= 1) sum += __shfl_xor_sync(0xffffffffu, sum, o);
    float mean = sum * (1.0f / D_);

    float vs = 0.f;
    #pragma unroll
    for (int i = 0; i < 4; i++) {
        float dx = v[i].x - mean, dy = v[i].y - mean;
        float dz = v[i].z - mean, dw = v[i].w - mean;
        vs += dx * dx + dy * dy + dz * dz + dw * dw;
    }
    #pragma unroll
    for (int o = 16; o; o >>= 1) vs += __shfl_xor_sync(0xffffffffu, vs, o);
    float inv = rsqrtf(vs * (1.0f / D_) + 1e-5f);

    const float4* sp = (const float4*)s;
    const float4* bp = (const float4*)b;
    half2 h2[8];
    #pragma unroll
    for (int i = 0; i < 4; i++) {
        float4 sv = sp[lane * 4 + i];
        float4 bv = bp[lane * 4 + i];
        float y0 = (v[i].x - mean) * inv * sv.x + bv.x;
        float y1 = (v[i].y - mean) * inv * sv.y + bv.y;
        float y2 = (v[i].z - mean) * inv * sv.z + bv.z;
        float y3 = (v[i].w - mean) * inv * sv.w + bv.w;
        h2[2 * i + 0] = __floats2half2_rn(y0, y1);
        h2[2 * i + 1] = __floats2half2_rn(y2, y3);
    }
    uint4* orow = (uint4*)(out + row * D_ + lane * 16);
    orow[0] = *(uint4*)&h2[0];
    orow[1] = *(uint4*)&h2[4];
}

// ------------------------- FP16 tensor-core GEMM (R13 config) --------------
// C[M,N] = A[M,K] * B^T[N,K]   (A [m][k] fp16, B [n][k] fp16)
// mode: 0 = fp16 store (QKV); 1 = +bias fp32 (logits);
//       2 = +bias relu fp16 (FF1); 3 = +bias +residual fp32 (proj, FF2)
// 128x128 CTA tile, 256 threads = 8 warps, warp tile 64(m) x 32(n), BK=32.
#define BK2 32
#define GROWB 80                 // row stride bytes
#define GBUFB (128 * 80)         // one buffer (one array) bytes = 10240
#define GEMM_SMEM (4 * GBUFB)    // 2 stages x (A + B) = 40960

__global__ __launch_bounds__(256, 2) void tgemm_kernel(
    const half* __restrict__ A, const half* __restrict__ Bm,
    const float* __restrict__ bias, const float* __restrict__ res,
    float* __restrict__ Cf, half* __restrict__ Ch,
    int M, int N, int K, int mode)
{
    extern __shared__ __align__(16) half smg[];
    uint32_t smBase = (uint32_t)__cvta_generic_to_shared(smg);
    const uint32_t BOFF = 2 * GBUFB;

    int tid  = threadIdx.x;
    int wid  = tid >> 5;
    int lane = tid & 31;
    int grp  = lane >> 2;
    int tig  = lane & 3;
    int warp_m = (wid & 1) * 64;
    int warp_n = (wid >> 1) * 32;

    int lrow = tid >> 2;
    int lc   = tid & 3;

    const half* Ap  = A + (size_t)(blockIdx.y * 128 + lrow) * K + lc * 8;
    const half* Ap2 = Ap + (size_t)64 * K;
    int gn  = blockIdx.x * 128 + lrow;
    int gn2 = gn + 64;
    bool bp  = gn  < N;
    bool bp2 = gn2 < N;
    const half* Bp  = Bm + (size_t)(bp  ? gn  : 0) * K + lc * 8;
    const half* Bp2 = Bm + (size_t)(bp2 ? gn2 : 0) * K + lc * 8;

    uint32_t aDst  = smBase + lrow * GROWB + lc * 16;
    uint32_t aDst2 = aDst + 64 * GROWB;
    uint32_t bDst  = smBase + BOFF + lrow * GROWB + lc * 16;
    uint32_t bDst2 = bDst + 64 * GROWB;

    uint32_t aLd = smBase + (warp_m + (lane & 7) + ((lane >> 3) & 1) * 8) * GROWB
                 + (lane >> 4) * 16;
    uint32_t bLd = smBase + BOFF + (warp_n + (lane & 7) + (lane >> 4) * 8) * GROWB
                 + ((lane >> 3) & 1) * 16;

    float acc[4][4][4];
    #pragma unroll
    for (int i = 0; i < 4; i++)
        #pragma unroll
        for (int j = 0; j < 4; j++)
            #pragma unroll
            for (int r = 0; r < 4; r++) acc[i][j][r] = 0.f;

    int nstage = K / BK2;

    // prologue: stage 0 -> buffer 0
    cp16(aDst, Ap, true);
    cp16(aDst2, Ap2, true);
    cp16(bDst, Bp, bp);
    cp16(bDst2, Bp2, bp2);
    cp_commit();
    cp_wait0();
    __syncthreads();

    int cur = 0;
    for (int s = 0; s < nstage; s++) {
        if (s + 1 < nstage) {
            int k0 = (s + 1) * BK2;
            uint32_t io = (cur ^ 1) * GBUFB;
            cp16(aDst + io, Ap + k0, true);
            cp16(aDst2 + io, Ap2 + k0, true);
            cp16(bDst + io, Bp + k0, bp);
            cp16(bDst2 + io, Bp2 + k0, bp2);
            cp_commit();
        }

        uint32_t bo = cur * GBUFB;
        #pragma unroll
        for (int ks = 0; ks < 2; ks++) {
            uint32_t af[4][4];
            #pragma unroll
            for (int i = 0; i < 4; i++)
                ldsm_x4(af[i], aLd + bo + i * (16 * GROWB) + ks * 32);
            uint32_t bq[2][4];
            #pragma unroll
            for (int jb = 0; jb < 2; jb++)
                ldsm_x4(bq[jb], bLd + bo + jb * (16 * GROWB) + ks * 32);
            #pragma unroll
            for (int i = 0; i < 4; i++)
                #pragma unroll
                for (int j = 0; j < 4; j++)
                    mma_f16(acc[i][j], af[i], &bq[j >> 1][2 * (j & 1)]);
        }

        if (s + 1 < nstage) {
            cp_wait0();
            __syncthreads();
            cur ^= 1;
        }
    }

    #pragma unroll
    for (int i = 0; i < 4; i++) {
        int row0 = blockIdx.y * 128 + warp_m + i * 16 + grp;
        #pragma unroll
        for (int j = 0; j < 4; j++) {
            int col = blockIdx.x * 128 + warp_n + j * 8 + 2 * tig;
            if (col < N) {
                #pragma unroll
                for (int hf = 0; hf < 2; hf++) {
                    int r = row0 + hf * 8;
                    size_t rb = (size_t)r * N;
                    float v0 = acc[i][j][hf * 2 + 0];
                    float v1 = acc[i][j][hf * 2 + 1];
                    if (mode >= 1) { v0 += bias[col]; v1 += bias[col + 1]; }
                    if (mode == 2) { v0 = fmaxf(v0, 0.f); v1 = fmaxf(v1, 0.f); }
                    if (mode == 0 || mode == 2) {
                        *(half2*)(Ch + rb + col) = __floats2half2_rn(v0, v1);
                    } else {
                        if (mode == 3) { v0 += res[rb + col]; v1 += res[rb + col + 1]; }
                        *(float2*)(Cf + rb + col) = make_float2(v0, v1);
                    }
                }
            }
        }
    }
}

// ------------------------- fp16 flash attention (P in registers) -----------
// 128 queries/block, 8 warps x 16 query-rows, 64-key tiles double-buffered.
#define KROWB 144
#define KVBUF (64 * KROWB)            // 9216
#define ATTN_SMEM (4 * KVBUF)         // 36864

__global__ __launch_bounds__(256, 2) void attn_kernel(const half* __restrict__ QKV,
                                                      half* __restrict__ O) {
    extern __shared__ __align__(16) half sma[];
    uint32_t smBase = (uint32_t)__cvta_generic_to_shared(sma);

    int b = blockIdx.y >> 3, h = blockIdx.y & 7;
    int qb = blockIdx.x * 128;
    int tid = threadIdx.x, wid = tid >> 5, lane = tid & 31;
    int grp = lane >> 2, tig = lane & 3;
    const float scale2 = 0.04419417382415922f * 1.4426950408889634f;

    int lr0 = wid * 16 + grp;
    int lr1 = lr0 + 8;
    int gr0 = qb + lr0, gr1 = qb + lr1;

    const half* q0p = QKV + ((size_t)(b * T_) + gr0) * 1536 + h * 64;
    const half* q1p = QKV + ((size_t)(b * T_) + gr1) * 1536 + h * 64;
    uint32_t qa[4][4];
    #pragma unroll
    for (int k = 0; k < 4; k++) {
        int dd = 16 * k + 2 * tig;
        #pragma unroll
        for (int r = 0; r < 4; r++) {
            const half* qp = (r & 1) ? q1p : q0p;
            int d2 = dd + (r >> 1) * 8;
            float2 f = __half22float2(*(const half2*)(qp + d2));
            half2 hv = __floats2half2_rn(f.x * scale2, f.y * scale2);
            qa[k][r] = *(uint32_t*)&hv;
        }
    }

    uint32_t kLd = smBase + ((lane & 7) + (lane >> 4) * 8) * KROWB
                 + ((lane >> 3) & 1) * 16;
    uint32_t vLd = smBase + 2 * KVBUF + ((lane & 7) + ((lane >> 3) & 1) * 8) * KROWB
                 + (lane >> 4) * 16;

    int key4 = tid >> 2, c4 = tid & 3;
    int dh = 8 * c4;
    uint32_t kDst = smBase + key4 * KROWB + dh * 2;
    uint32_t vDst = kDst + 2 * KVBUF;
    const half* kvb = QKV + (size_t)(b * T_) * 1536 + h * 64 + D_;
    const half* kRow = kvb + (size_t)key4 * 1536 + dh;

    float o[8][4];
    #pragma unroll
    for (int j = 0; j < 8; j++) { o[j][0] = o[j][1] = o[j][2] = o[j][3] = 0.f; }
    float m0 = -1e30f, m1 = -1e30f, l0 = 0.f, l1 = 0.f;

    int ntiles = (qb >> 6) + 2;

    {
        cp16(kDst,      kRow,        true);
        cp16(kDst + 64, kRow + 32,   true);
        cp16(vDst,      kRow + 512,  true);
        cp16(vDst + 64, kRow + 544,  true);
        cp_commit();
    }

    for (int t = 0; t < ntiles; t++) {
        cp_wait0();
        __syncthreads();

        if (t + 1 < ntiles) {
            uint32_t io = ((t + 1) & 1) * KVBUF;
            const half* kr = kRow + (size_t)(t + 1) * 64 * 1536;
            cp16(kDst + io,      kr,       true);
            cp16(kDst + io + 64, kr + 32,  true);
            cp16(vDst + io,      kr + 512, true);
            cp16(vDst + io + 64, kr + 544, true);
            cp_commit();
        }

        uint32_t bo = (t & 1) * KVBUF;
        int k0 = t * 64;

        float sc[8][4];
        #pragma unroll
        for (int j = 0; j < 8; j++) { sc[j][0] = sc[j][1] = sc[j][2] = sc[j][3] = 0.f; }
        #pragma unroll
        for (int kd = 0; kd < 4; kd++) {
            uint32_t kq[4][4];
            #pragma unroll
            for (int jp = 0; jp < 4; jp++)
                ldsm_x4(kq[jp], kLd + bo + jp * (16 * KROWB) + kd * 32);
            #pragma unroll
            for (int j = 0; j < 8; j++)
                mma_f16(sc[j], qa[kd], &kq[j >> 1][2 * (j & 1)]);
        }

        if (k0 + 63 > qb + wid * 16) {
            #pragma unroll
            for (int j = 0; j < 8; j++) {
                int key = k0 + 8 * j + 2 * tig;
                if (key     > gr0) sc[j][0] = -1e30f;
                if (key + 1 > gr0) sc[j][1] = -1e30f;
                if (key     > gr1) sc[j][2] = -1e30f;
                if (key + 1 > gr1) sc[j][3] = -1e30f;
            }
        }

        float mx0 = -1e30f, mx1 = -1e30f;
        #pragma unroll
        for (int j = 0; j < 8; j++) {
            mx0 = fmaxf(mx0, fmaxf(sc[j][0], sc[j][1]));
            mx1 = fmaxf(mx1, fmaxf(sc[j][2], sc[j][3]));
        }
        mx0 = fmaxf(mx0, __shfl_xor_sync(0xffffffffu, mx0, 1));
        mx0 = fmaxf(mx0, __shfl_xor_sync(0xffffffffu, mx0, 2));
        mx1 = fmaxf(mx1, __shfl_xor_sync(0xffffffffu, mx1, 1));
        mx1 = fmaxf(mx1, __shfl_xor_sync(0xffffffffu, mx1, 2));
        float mn0 = fmaxf(m0, mx0), mn1 = fmaxf(m1, mx1);
        float c0 = ex2(m0 - mn0), c1 = ex2(m1 - mn1);
        m0 = mn0; m1 = mn1;

        uint32_t pf[4][4];
        float s0 = 0.f, s1 = 0.f;
        #pragma unroll
        for (int k = 0; k < 4; k++) {
            float p00 = ex2(sc[2 * k][0] - m0);
            float p01 = ex2(sc[2 * k][1] - m0);
            float p02 = ex2(sc[2 * k][2] - m1);
            float p03 = ex2(sc[2 * k][3] - m1);
            float p10 = ex2(sc[2 * k + 1][0] - m0);
            float p11 = ex2(sc[2 * k + 1][1] - m0);
            float p12 = ex2(sc[2 * k + 1][2] - m1);
            float p13 = ex2(sc[2 * k + 1][3] - m1);
            s0 += p00 + p01 + p10 + p11;
            s1 += p02 + p03 + p12 + p13;
            half2 h0 = __floats2half2_rn(p00, p01);
            half2 h1 = __floats2half2_rn(p02, p03);
            half2 h2 = __floats2half2_rn(p10, p11);
            half2 h3 = __floats2half2_rn(p12, p13);
            pf[k][0] = *(uint32_t*)&h0;
            pf[k][1] = *(uint32_t*)&h1;
            pf[k][2] = *(uint32_t*)&h2;
            pf[k][3] = *(uint32_t*)&h3;
        }
        s0 += __shfl_xor_sync(0xffffffffu, s0, 1);
        s0 += __shfl_xor_sync(0xffffffffu, s0, 2);
        s1 += __shfl_xor_sync(0xffffffffu, s1, 1);
        s1 += __shfl_xor_sync(0xffffffffu, s1, 2);
        l0 = l0 * c0 + s0;
        l1 = l1 * c1 + s1;
        #pragma unroll
        for (int j = 0; j < 8; j++) {
            o[j][0] *= c0; o[j][1] *= c0; o[j][2] *= c1; o[j][3] *= c1;
        }

        #pragma unroll
        for (int kd = 0; kd < 4; kd++) {
            uint32_t vq[4][4];
            #pragma unroll
            for (int jp = 0; jp < 4; jp++)
                ldsm_x4_t(vq[jp], vLd + bo + kd * (16 * KROWB) + jp * 32);
            #pragma unroll
            for (int j = 0; j < 8; j++)
                mma_f16(o[j], pf[kd], &vq[j >> 1][2 * (j & 1)]);
        }
    }

    float i0 = 1.f / l0, i1 = 1.f / l1;
    size_t ob0 = ((size_t)(b * T_) + gr0) * D_ + h * 64;
    size_t ob1 = ((size_t)(b * T_) + gr1) * D_ + h * 64;
    #pragma unroll
    for (int j = 0; j < 8; j++) {
        int c = 8 * j + 2 * tig;
        *(half2*)(O + ob0 + c) = __floats2half2_rn(o[j][0] * i0, o[j][1] * i0);
        *(half2*)(O + ob1 + c) = __floats2half2_rn(o[j][2] * i1, o[j][3] * i1);
    }
}

// ------------------------- loss --------------------------------------------
__global__ __launch_bounds__(256) void loss_kernel(const float* __restrict__ logits,
                                                   const int* __restrict__ targets,
                                                   double* __restrict__ acc) {
    int warp = (blockIdx.x * blockDim.x + threadIdx.x) >> 5;
    int lane = threadIdx.x & 31;
    const float* lr = logits + (size_t)warp * V_;
    float v0 = lr[lane], v1 = lr[lane + 32], v2 = lr[lane + 64];
    float m = fmaxf(v0, fmaxf(v1, v2));
    #pragma unroll
    for (int o = 16; o; o >>= 1) m = fmaxf(m, __shfl_xor_sync(0xffffffffu, m, o));
    float se = expf(v0 - m) + expf(v1 - m) + expf(v2 - m);
    #pragma unroll
    for (int o = 16; o; o >>= 1) se += __shfl_xor_sync(0xffffffffu, se, o);

    __shared__ float part[8];
    if (lane == 0) part[threadIdx.x >> 5] = lr[targets[warp]] - m - logf(se);
    __syncthreads();
    if (threadIdx.x == 0) {
        float s = 0.f;
        #pragma unroll
        for (int i = 0; i < 8; i++) s += part[i];
        atomicAdd(acc, (double)s);
    }
}

__global__ void finalize_loss_kernel(float* out, const double* acc) {
    out[(size_t)BT_ * V_] = (float)(-(*acc) / (double)BT_);
}

// ------------------------- launcher ----------------------------------------
extern "C" void kernel_launch(void* const* d_in, const int* in_sizes, int n_in,
                              void* d_out, int out_size) {
    const int*   idx     = (const int*)  d_in[0];
    const int*   targets = (const int*)  d_in[1];
    const float* tok     = (const float*)d_in[2];
    const float* pos     = (const float*)d_in[3];
    const float* Wq      = (const float*)d_in[4];
    const float* Wk      = (const float*)d_in[5];
    const float* Wv      = (const float*)d_in[6];
    const float* Wproj   = (const float*)d_in[7];
    const float* bproj   = (const float*)d_in[8];
    const float* W1      = (const float*)d_in[9];
    const float* b1      = (const float*)d_in[10];
    const float* W2      = (const float*)d_in[11];
    const float* b2      = (const float*)d_in[12];
    const float* ln1_s   = (const float*)d_in[13];
    const float* ln1_b   = (const float*)d_in[14];
    const float* ln2_s   = (const float*)d_in[15];
    const float* ln2_b   = (const float*)d_in[16];
    const float* lnf_s   = (const float*)d_in[17];
    const float* lnf_b   = (const float*)d_in[18];
    const float* Wout    = (const float*)d_in[19];
    const float* bout    = (const float*)d_in[20];
    float* out = (float*)d_out;

    float* x;
    half *h, *qkv, *o, *ff, *wqkv, *wproj, *w1, *w2, *wout;
    double* lossAcc;
    cudaGetSymbolAddress((void**)&x,    g_x);
    cudaGetSymbolAddress((void**)&qkv,  g_qkv);
    cudaGetSymbolAddress((void**)&h,    g_h);
    cudaGetSymbolAddress((void**)&o,    g_o);
    cudaGetSymbolAddress((void**)&ff,   g_ff);
    cudaGetSymbolAddress((void**)&wqkv, g_wqkv);
    cudaGetSymbolAddress((void**)&wproj, g_wproj);
    cudaGetSymbolAddress((void**)&w1,   g_w1);
    cudaGetSymbolAddress((void**)&w2,   g_w2);
    cudaGetSymbolAddress((void**)&wout, g_wout);
    cudaGetSymbolAddress((void**)&lossAcc, g_loss);

    cudaFuncSetAttribute(tgemm_kernel,
                         cudaFuncAttributeMaxDynamicSharedMemorySize, GEMM_SMEM);
    cudaFuncSetAttribute(attn_kernel,
                         cudaFuncAttributeMaxDynamicSharedMemorySize, ATTN_SMEM);

    // weight packing (coalesced transposes, fp16)
    {
        dim3 blk(32, 8);
        pack_qkv_kernel<<<dim3(D_ / 32, HS_ / 32, L_ * 3 * H_), blk>>>(Wq, Wk, Wv, wqkv);
        pack_wt_kernel<<<dim3(D_ / 32, D_ / 32, L_), blk>>>(Wproj, wproj, D_, D_);
        pack_wt_kernel<<<dim3(FF_ / 32, D_ / 32, L_), blk>>>(W1, w1, D_, FF_);
        pack_wt_kernel<<<dim3(D_ / 32, FF_ / 32, L_), blk>>>(W2, w2, FF_, D_);
        pack_wt_kernel<<<dim3(V_ / 32, D_ / 32, 1), blk>>>(Wout, wout, D_, V_);
    }
    {
        int total = BT_ * D_;
        embed_kernel<<<(total + 255) / 256, 256>>>(idx, tok, pos, x);
    }

    const int MT = BT_ / 128;  // 128 M-tiles
    const int LNG = BT_ / 8;   // LN grid (8 rows/block)
    for (int l = 0; l < L_; l++) {
        ln_kernel<<<LNG, 256>>>(x, ln1_s + l * D_, ln1_b + l * D_, h);
        tgemm_kernel<<<dim3(12, MT), 256, GEMM_SMEM>>>(
            h, wqkv + (size_t)l * 3 * D_ * D_,
            nullptr, nullptr, nullptr, qkv, BT_, 3 * D_, D_, 0);
        attn_kernel<<<dim3(T_ / 128, B_ * H_), 256, ATTN_SMEM>>>(qkv, o);
        tgemm_kernel<<<dim3(4, MT), 256, GEMM_SMEM>>>(
            o, wproj + (size_t)l * D_ * D_,
            bproj + l * D_, x, x, nullptr, BT_, D_, D_, 3);
        ln_kernel<<<LNG, 256>>>(x, ln2_s + l * D_, ln2_b + l * D_, h);
        tgemm_kernel<<<dim3(16, MT), 256, GEMM_SMEM>>>(
            h, w1 + (size_t)l * FF_ * D_,
            b1 + l * FF_, nullptr, nullptr, ff, BT_, FF_, D_, 2);
        tgemm_kernel<<<dim3(4, MT), 256, GEMM_SMEM>>>(
            ff, w2 + (size_t)l * D_ * FF_,
            b2 + l * D_, x, x, nullptr, BT_, D_, FF_, 3);
    }

    ln_kernel<<<LNG, 256>>>(x, lnf_s, lnf_b, h);
    tgemm_kernel<<<dim3(1, MT), 256, GEMM_SMEM>>>(
        h, wout, bout, nullptr, out, nullptr, BT_, V_, D_, 1);

    if (out_size > BT_ * V_) {
        zero_loss_kernel<<<1, 1>>>(lossAcc);
        loss_kernel<<<BT_ / 8, 256>>>(out, targets, lossAcc);
        finalize_loss_kernel<<<1, 1>>>(out, lossAcc);
    }
}